// round 1
// baseline (speedup 1.0000x reference)
#include <cuda_runtime.h>
#include <math.h>

static constexpr int Bb = 8, Nn = 2048, Mm = 2048, Cc = 512;

// Scratch (static __device__ arrays — sanctioned; no allocations)
__device__ float S_buf[(size_t)Bb * Nn * Mm];   // scores -> probs (in place), 128 MiB
__device__ float V_buf[(size_t)Bb * Mm * Cc];   // enc@Wv+bv
__device__ float G_buf[(size_t)Bb * Nn * Cc];   // gated
__device__ float H_buf[(size_t)Bb * Nn * Cc];   // relu(fc1)

#define BM 128
#define BN 128
#define BK 8
#define NT 256

// ---------------------------------------------------------------------------
// Generic fp32 GEMM: C[Md,Nd] = A[Md,Kd] @ B[Kd,Nd] + bias[Nd], EPI 0=bias 1=bias+relu
// 256 threads, 8x8 micro-tile split into four 4x4 quadrants (conflict-free LDS.128)
// ---------------------------------------------------------------------------
template <int EPI>
__global__ __launch_bounds__(NT) void gemm_bias(
    const float* __restrict__ A, const float* __restrict__ Bm,
    const float* __restrict__ bias, float* __restrict__ Cout,
    int Md, int Nd, int Kd)
{
    __shared__ float As[BK][BM];
    __shared__ float Bs[BK][BN];
    const int tid = threadIdx.x;
    const int bx = blockIdx.x, by = blockIdx.y;

    const int aRow = tid >> 1, aCol = (tid & 1) * 4;
    const int bRow = tid >> 5, bCol = (tid & 31) * 4;
    const float* Ap = A + (size_t)(by * BM + aRow) * Kd + aCol;
    const float* Bp = Bm + (size_t)bRow * Nd + bx * BN + bCol;

    const int tr0 = (tid >> 4) * 4;   // 0..60
    const int tc0 = (tid & 15) * 4;   // 0..60
    float acc[8][8];
    #pragma unroll
    for (int i = 0; i < 8; i++)
        #pragma unroll
        for (int j = 0; j < 8; j++) acc[i][j] = 0.f;

    for (int k0 = 0; k0 < Kd; k0 += BK) {
        float4 a4 = *(const float4*)Ap;
        As[aCol + 0][aRow] = a4.x; As[aCol + 1][aRow] = a4.y;
        As[aCol + 2][aRow] = a4.z; As[aCol + 3][aRow] = a4.w;
        *(float4*)&Bs[bRow][bCol] = *(const float4*)Bp;
        __syncthreads();
        #pragma unroll
        for (int k = 0; k < BK; k++) {
            float4 a0 = *(const float4*)&As[k][tr0];
            float4 a1 = *(const float4*)&As[k][tr0 + 64];
            float4 b0 = *(const float4*)&Bs[k][tc0];
            float4 b1 = *(const float4*)&Bs[k][tc0 + 64];
            float ar[8] = {a0.x, a0.y, a0.z, a0.w, a1.x, a1.y, a1.z, a1.w};
            float br[8] = {b0.x, b0.y, b0.z, b0.w, b1.x, b1.y, b1.z, b1.w};
            #pragma unroll
            for (int i = 0; i < 8; i++)
                #pragma unroll
                for (int j = 0; j < 8; j++)
                    acc[i][j] = fmaf(ar[i], br[j], acc[i][j]);
        }
        __syncthreads();
        Ap += BK;
        Bp += (size_t)BK * Nd;
    }

    const int orow = by * BM + tr0, ocol = bx * BN + tc0;
    #pragma unroll
    for (int i = 0; i < 8; i++) {
        int r = orow + ((i >> 2) * 64) + (i & 3);
        #pragma unroll
        for (int jh = 0; jh < 2; jh++) {
            int c = ocol + jh * 64;
            float4 o;
            o.x = acc[i][jh * 4 + 0] + bias[c + 0];
            o.y = acc[i][jh * 4 + 1] + bias[c + 1];
            o.z = acc[i][jh * 4 + 2] + bias[c + 2];
            o.w = acc[i][jh * 4 + 3] + bias[c + 3];
            if (EPI == 1) {
                o.x = fmaxf(o.x, 0.f); o.y = fmaxf(o.y, 0.f);
                o.z = fmaxf(o.z, 0.f); o.w = fmaxf(o.w, 0.f);
            }
            *(float4*)&Cout[(size_t)r * Nd + c] = o;
        }
    }
}

// ---------------------------------------------------------------------------
// Scores: S[b][n,m] = (dec[b,n,:] . enc[b,m,:]) * mask[b,n,m]   (A @ B^T)
// ---------------------------------------------------------------------------
__global__ __launch_bounds__(NT) void score_kernel(
    const float* __restrict__ dec, const float* __restrict__ enc,
    const float* __restrict__ mask, float* __restrict__ Sout)
{
    __shared__ float As[BK][BM];
    __shared__ float Bs[BK][BN];
    const int b = blockIdx.z;
    const int tid = threadIdx.x;
    const int bx = blockIdx.x, by = blockIdx.y;

    const float* A  = dec  + (size_t)b * Nn * Cc;
    const float* E  = enc  + (size_t)b * Mm * Cc;
    const float* Mk = mask + (size_t)b * Nn * Mm;
    float*       S  = Sout + (size_t)b * Nn * Mm;

    const int aRow = tid >> 1, aCol = (tid & 1) * 4;
    const float* Ap = A + (size_t)(by * BM + aRow) * Cc + aCol;
    const float* Ep = E + (size_t)(bx * BN + aRow) * Cc + aCol;  // same thread pattern

    const int tr0 = (tid >> 4) * 4;
    const int tc0 = (tid & 15) * 4;
    float acc[8][8];
    #pragma unroll
    for (int i = 0; i < 8; i++)
        #pragma unroll
        for (int j = 0; j < 8; j++) acc[i][j] = 0.f;

    for (int k0 = 0; k0 < Cc; k0 += BK) {
        float4 a4 = *(const float4*)Ap;
        As[aCol + 0][aRow] = a4.x; As[aCol + 1][aRow] = a4.y;
        As[aCol + 2][aRow] = a4.z; As[aCol + 3][aRow] = a4.w;
        float4 e4 = *(const float4*)Ep;
        Bs[aCol + 0][aRow] = e4.x; Bs[aCol + 1][aRow] = e4.y;
        Bs[aCol + 2][aRow] = e4.z; Bs[aCol + 3][aRow] = e4.w;
        __syncthreads();
        #pragma unroll
        for (int k = 0; k < BK; k++) {
            float4 a0 = *(const float4*)&As[k][tr0];
            float4 a1 = *(const float4*)&As[k][tr0 + 64];
            float4 b0 = *(const float4*)&Bs[k][tc0];
            float4 b1 = *(const float4*)&Bs[k][tc0 + 64];
            float ar[8] = {a0.x, a0.y, a0.z, a0.w, a1.x, a1.y, a1.z, a1.w};
            float br[8] = {b0.x, b0.y, b0.z, b0.w, b1.x, b1.y, b1.z, b1.w};
            #pragma unroll
            for (int i = 0; i < 8; i++)
                #pragma unroll
                for (int j = 0; j < 8; j++)
                    acc[i][j] = fmaf(ar[i], br[j], acc[i][j]);
        }
        __syncthreads();
        Ap += BK;
        Ep += BK;
    }

    const int orow = by * BM + tr0, ocol = bx * BN + tc0;
    #pragma unroll
    for (int i = 0; i < 8; i++) {
        int r = orow + ((i >> 2) * 64) + (i & 3);
        #pragma unroll
        for (int jh = 0; jh < 2; jh++) {
            int c = ocol + jh * 64;
            float4 mk = *(const float4*)&Mk[(size_t)r * Mm + c];
            float4 o;
            o.x = acc[i][jh * 4 + 0] * mk.x;
            o.y = acc[i][jh * 4 + 1] * mk.y;
            o.z = acc[i][jh * 4 + 2] * mk.z;
            o.w = acc[i][jh * 4 + 3] * mk.w;
            *(float4*)&S[(size_t)r * Mm + c] = o;
        }
    }
}

// ---------------------------------------------------------------------------
// Nonstandard masked softmax, in place on S_buf rows of length M.
// denom = sum over ALL entries of exp(v - rowmax) (zeros contribute exp(-max));
// then P = (v != 0) ? exp(v - max)/denom : 0.
// ---------------------------------------------------------------------------
__global__ __launch_bounds__(256) void softmax_kernel(float* __restrict__ Sbuf)
{
    float* S = Sbuf + (size_t)blockIdx.x * Mm;
    const int tid = threadIdx.x;

    float4 u0 = *(const float4*)&S[tid * 8];
    float4 u1 = *(const float4*)&S[tid * 8 + 4];
    float v[8] = {u0.x, u0.y, u0.z, u0.w, u1.x, u1.y, u1.z, u1.w};

    float mx = v[0];
    #pragma unroll
    for (int i = 1; i < 8; i++) mx = fmaxf(mx, v[i]);
    #pragma unroll
    for (int o = 16; o > 0; o >>= 1) mx = fmaxf(mx, __shfl_xor_sync(0xffffffffu, mx, o));

    __shared__ float red[8];
    const int wid = tid >> 5, lid = tid & 31;
    if (lid == 0) red[wid] = mx;
    __syncthreads();
    float rmax = red[0];
    #pragma unroll
    for (int w = 1; w < 8; w++) rmax = fmaxf(rmax, red[w]);
    __syncthreads();

    float s = 0.f;
    #pragma unroll
    for (int i = 0; i < 8; i++) s += __expf(v[i] - rmax);
    #pragma unroll
    for (int o = 16; o > 0; o >>= 1) s += __shfl_xor_sync(0xffffffffu, s, o);
    if (lid == 0) red[wid] = s;
    __syncthreads();
    float tot = 0.f;
    #pragma unroll
    for (int w = 0; w < 8; w++) tot += red[w];
    const float inv = 1.f / tot;

    float p[8];
    #pragma unroll
    for (int i = 0; i < 8; i++)
        p[i] = (v[i] != 0.f) ? __expf(v[i] - rmax) * inv : 0.f;
    *(float4*)&S[tid * 8]     = make_float4(p[0], p[1], p[2], p[3]);
    *(float4*)&S[tid * 8 + 4] = make_float4(p[4], p[5], p[6], p[7]);
}

// ---------------------------------------------------------------------------
// O = P @ V, then g = dec * (1 + tanh(O))  -> G_buf
// ---------------------------------------------------------------------------
__global__ __launch_bounds__(NT) void av_kernel(
    const float* __restrict__ dec, const float* __restrict__ P,
    const float* __restrict__ V, float* __restrict__ G)
{
    __shared__ float As[BK][BM];
    __shared__ float Bs[BK][BN];
    const int b = blockIdx.z;
    const int tid = threadIdx.x;
    const int bx = blockIdx.x, by = blockIdx.y;

    const float* A  = P + (size_t)b * Nn * Mm;
    const float* Bm = V + (size_t)b * Mm * Cc;
    const float* Db = dec + (size_t)b * Nn * Cc;
    float*       Gb = G + (size_t)b * Nn * Cc;

    const int aRow = tid >> 1, aCol = (tid & 1) * 4;
    const int bRow = tid >> 5, bCol = (tid & 31) * 4;
    const float* Ap = A + (size_t)(by * BM + aRow) * Mm + aCol;
    const float* Bp = Bm + (size_t)bRow * Cc + bx * BN + bCol;

    const int tr0 = (tid >> 4) * 4;
    const int tc0 = (tid & 15) * 4;
    float acc[8][8];
    #pragma unroll
    for (int i = 0; i < 8; i++)
        #pragma unroll
        for (int j = 0; j < 8; j++) acc[i][j] = 0.f;

    for (int k0 = 0; k0 < Mm; k0 += BK) {
        float4 a4 = *(const float4*)Ap;
        As[aCol + 0][aRow] = a4.x; As[aCol + 1][aRow] = a4.y;
        As[aCol + 2][aRow] = a4.z; As[aCol + 3][aRow] = a4.w;
        *(float4*)&Bs[bRow][bCol] = *(const float4*)Bp;
        __syncthreads();
        #pragma unroll
        for (int k = 0; k < BK; k++) {
            float4 a0 = *(const float4*)&As[k][tr0];
            float4 a1 = *(const float4*)&As[k][tr0 + 64];
            float4 b0 = *(const float4*)&Bs[k][tc0];
            float4 b1 = *(const float4*)&Bs[k][tc0 + 64];
            float ar[8] = {a0.x, a0.y, a0.z, a0.w, a1.x, a1.y, a1.z, a1.w};
            float br[8] = {b0.x, b0.y, b0.z, b0.w, b1.x, b1.y, b1.z, b1.w};
            #pragma unroll
            for (int i = 0; i < 8; i++)
                #pragma unroll
                for (int j = 0; j < 8; j++)
                    acc[i][j] = fmaf(ar[i], br[j], acc[i][j]);
        }
        __syncthreads();
        Ap += BK;
        Bp += (size_t)BK * Cc;
    }

    const int orow = by * BM + tr0, ocol = bx * BN + tc0;
    #pragma unroll
    for (int i = 0; i < 8; i++) {
        int r = orow + ((i >> 2) * 64) + (i & 3);
        #pragma unroll
        for (int jh = 0; jh < 2; jh++) {
            int c = ocol + jh * 64;
            float4 d4 = *(const float4*)&Db[(size_t)r * Cc + c];
            float4 o;
            o.x = d4.x * (1.f + tanhf(acc[i][jh * 4 + 0]));
            o.y = d4.y * (1.f + tanhf(acc[i][jh * 4 + 1]));
            o.z = d4.z * (1.f + tanhf(acc[i][jh * 4 + 2]));
            o.w = d4.w * (1.f + tanhf(acc[i][jh * 4 + 3]));
            *(float4*)&Gb[(size_t)r * Cc + c] = o;
        }
    }
}

// ---------------------------------------------------------------------------
extern "C" void kernel_launch(void* const* d_in, const int* in_sizes, int n_in,
                              void* d_out, int out_size)
{
    const float* dec  = (const float*)d_in[0];
    const float* enc  = (const float*)d_in[1];
    const float* mask = (const float*)d_in[2];
    const float* Wv   = (const float*)d_in[3];
    const float* bv   = (const float*)d_in[4];
    const float* W1   = (const float*)d_in[5];
    const float* b1   = (const float*)d_in[6];
    const float* W2   = (const float*)d_in[7];
    const float* b2   = (const float*)d_in[8];
    float* out = (float*)d_out;

    float *S, *V, *G, *H;
    cudaGetSymbolAddress((void**)&S, S_buf);
    cudaGetSymbolAddress((void**)&V, V_buf);
    cudaGetSymbolAddress((void**)&G, G_buf);
    cudaGetSymbolAddress((void**)&H, H_buf);

    // K1: V = enc @ Wv + bv     ([B*M, C] x [C, C])
    gemm_bias<0><<<dim3(Cc / BN, (Bb * Mm) / BM), NT>>>(enc, Wv, bv, V,
                                                        Bb * Mm, Cc, Cc);
    // K2: S = (dec @ enc^T) * mask
    score_kernel<<<dim3(Mm / BN, Nn / BM, Bb), NT>>>(dec, enc, mask, S);
    // K3: nonstandard softmax in place
    softmax_kernel<<<Bb * Nn, 256>>>(S);
    // K4: G = dec * (1 + tanh(P @ V))
    av_kernel<<<dim3(Cc / BN, Nn / BM, Bb), NT>>>(dec, S, V, G);
    // K5: H = relu(G @ W1 + b1)
    gemm_bias<1><<<dim3(Cc / BN, (Bb * Nn) / BM), NT>>>(G, W1, b1, H,
                                                        Bb * Nn, Cc, Cc);
    // K6: out = H @ W2 + b2
    gemm_bias<0><<<dim3(Cc / BN, (Bb * Nn) / BM), NT>>>(H, W2, b2, out,
                                                        Bb * Nn, Cc, Cc);
}

// round 3
// speedup vs baseline: 3.5584x; 3.5584x over previous
#include <cuda_runtime.h>
#include <cuda_bf16.h>
#include <cstdint>
#include <math.h>

typedef __nv_bfloat16 bf16;

static constexpr int Bb = 8, Nn = 2048, Mm = 2048, Cc = 512;

// ---------------- scratch (__device__ globals; no allocations) ----------------
__device__ float S_buf [(size_t)Bb * Nn * Mm];          // scores fp32 (128 MiB)
__device__ bf16  Ph_buf[(size_t)Bb * Nn * Mm];          // softmax probs hi
__device__ bf16  Pl_buf[(size_t)Bb * Nn * Mm];          // softmax probs lo
__device__ bf16  dech_buf[(size_t)Bb * Nn * Cc], decl_buf[(size_t)Bb * Nn * Cc];
__device__ bf16  ench_buf[(size_t)Bb * Mm * Cc], encl_buf[(size_t)Bb * Mm * Cc];
__device__ float Vf_buf [(size_t)Bb * Mm * Cc];         // enc@Wv+bv fp32
__device__ bf16  VTh_buf[(size_t)Bb * Cc * Mm], VTl_buf[(size_t)Bb * Cc * Mm];
__device__ bf16  Gh_buf[(size_t)Bb * Nn * Cc], Gl_buf[(size_t)Bb * Nn * Cc];
__device__ bf16  Hh_buf[(size_t)Bb * Nn * Cc], Hl_buf[(size_t)Bb * Nn * Cc];
__device__ bf16  WvTh_buf[Cc * Cc], WvTl_buf[Cc * Cc];
__device__ bf16  W1Th_buf[Cc * Cc], W1Tl_buf[Cc * Cc];
__device__ bf16  W2Th_buf[Cc * Cc], W2Tl_buf[Cc * Cc];

// ---------------- PTX helpers (arch-neutral only: cp.async / ldmatrix / mma.sync) ----
__device__ __forceinline__ uint32_t smem_u32(const void* p) {
    uint32_t a;
    asm("{ .reg .u64 t; cvta.to.shared.u64 t, %1; cvt.u32.u64 %0, t; }" : "=r"(a) : "l"(p));
    return a;
}
__device__ __forceinline__ void cp_async16(uint32_t dst, const void* src) {
    asm volatile("cp.async.cg.shared.global [%0], [%1], 16;" :: "r"(dst), "l"(src) : "memory");
}
__device__ __forceinline__ void cp_commit() { asm volatile("cp.async.commit_group;" ::: "memory"); }
template <int N> __device__ __forceinline__ void cp_wait() {
    asm volatile("cp.async.wait_group %0;" :: "n"(N) : "memory");
}
__device__ __forceinline__ void ldsm_x4(uint32_t* r, uint32_t addr) {
    asm volatile("ldmatrix.sync.aligned.m8n8.x4.shared.b16 {%0,%1,%2,%3}, [%4];"
        : "=r"(r[0]), "=r"(r[1]), "=r"(r[2]), "=r"(r[3]) : "r"(addr));
}
__device__ __forceinline__ void mma16816(float* c, const uint32_t* a, const uint32_t* b) {
    asm volatile("mma.sync.aligned.m16n8k16.row.col.f32.bf16.bf16.f32 "
        "{%0,%1,%2,%3}, {%4,%5,%6,%7}, {%8,%9}, {%0,%1,%2,%3};"
        : "+f"(c[0]), "+f"(c[1]), "+f"(c[2]), "+f"(c[3])
        : "r"(a[0]), "r"(a[1]), "r"(a[2]), "r"(a[3]), "r"(b[0]), "r"(b[1]));
}

// ---------------- conversion / transpose kernels ----------------
__global__ void split_kernel(const float* __restrict__ in, bf16* __restrict__ oh,
                             bf16* __restrict__ ol, size_t n4) {
    size_t i = (size_t)blockIdx.x * blockDim.x + threadIdx.x;
    if (i >= n4) return;
    float4 v = ((const float4*)in)[i];
    bf16 h0 = __float2bfloat16(v.x), h1 = __float2bfloat16(v.y);
    bf16 h2 = __float2bfloat16(v.z), h3 = __float2bfloat16(v.w);
    ((__nv_bfloat162*)oh)[2 * i]     = __nv_bfloat162(h0, h1);
    ((__nv_bfloat162*)oh)[2 * i + 1] = __nv_bfloat162(h2, h3);
    ((__nv_bfloat162*)ol)[2 * i] = __nv_bfloat162(
        __float2bfloat16(v.x - __bfloat162float(h0)), __float2bfloat16(v.y - __bfloat162float(h1)));
    ((__nv_bfloat162*)ol)[2 * i + 1] = __nv_bfloat162(
        __float2bfloat16(v.z - __bfloat162float(h2)), __float2bfloat16(v.w - __bfloat162float(h3)));
}

// out[c][r] = in[r][c]; in: [rows, cols] fp32, out: [cols, rows] bf16 hi/lo
__global__ void transpose_split(const float* __restrict__ in, bf16* __restrict__ oh,
                                bf16* __restrict__ ol, int rows, int cols,
                                size_t ibs, size_t obs) {
    __shared__ float t[32][33];
    const float* I = in + (size_t)blockIdx.z * ibs;
    bf16* OH = oh + (size_t)blockIdx.z * obs;
    bf16* OL = ol + (size_t)blockIdx.z * obs;
    int c0 = blockIdx.x * 32, r0 = blockIdx.y * 32;
    int tx = threadIdx.x, ty = threadIdx.y;
    #pragma unroll
    for (int k = 0; k < 4; k++)
        t[ty + 8 * k][tx] = I[(size_t)(r0 + ty + 8 * k) * cols + c0 + tx];
    __syncthreads();
    #pragma unroll
    for (int k = 0; k < 4; k++) {
        float v = t[tx][ty + 8 * k];
        size_t o = (size_t)(c0 + ty + 8 * k) * rows + r0 + tx;
        bf16 h = __float2bfloat16(v);
        OH[o] = h;
        OL[o] = __float2bfloat16(v - __bfloat162float(h));
    }
}

// ---------------- nonstandard masked softmax: S fp32 -> P hi/lo bf16 ----------------
__global__ __launch_bounds__(256) void softmax_kernel(const float* __restrict__ Sb,
                                                      bf16* __restrict__ Ph, bf16* __restrict__ Pl) {
    const float* S = Sb + (size_t)blockIdx.x * Mm;
    bf16* PH = Ph + (size_t)blockIdx.x * Mm;
    bf16* PL = Pl + (size_t)blockIdx.x * Mm;
    const int tid = threadIdx.x;

    float4 u0 = *(const float4*)&S[tid * 8];
    float4 u1 = *(const float4*)&S[tid * 8 + 4];
    float v[8] = {u0.x, u0.y, u0.z, u0.w, u1.x, u1.y, u1.z, u1.w};

    float mx = v[0];
    #pragma unroll
    for (int i = 1; i < 8; i++) mx = fmaxf(mx, v[i]);
    #pragma unroll
    for (int o = 16; o > 0; o >>= 1) mx = fmaxf(mx, __shfl_xor_sync(0xffffffffu, mx, o));

    __shared__ float red[8];
    const int wid = tid >> 5, lid = tid & 31;
    if (lid == 0) red[wid] = mx;
    __syncthreads();
    float rmax = red[0];
    #pragma unroll
    for (int w = 1; w < 8; w++) rmax = fmaxf(rmax, red[w]);
    __syncthreads();

    float s = 0.f;
    #pragma unroll
    for (int i = 0; i < 8; i++) s += __expf(v[i] - rmax);
    #pragma unroll
    for (int o = 16; o > 0; o >>= 1) s += __shfl_xor_sync(0xffffffffu, s, o);
    if (lid == 0) red[wid] = s;
    __syncthreads();
    float tot = 0.f;
    #pragma unroll
    for (int w = 0; w < 8; w++) tot += red[w];
    const float inv = 1.f / tot;

    bf16 ph[8], pl[8];
    #pragma unroll
    for (int i = 0; i < 8; i++) {
        float p = (v[i] != 0.f) ? __expf(v[i] - rmax) * inv : 0.f;
        ph[i] = __float2bfloat16(p);
        pl[i] = __float2bfloat16(p - __bfloat162float(ph[i]));
    }
    *(uint4*)&PH[tid * 8] = *(uint4*)ph;
    *(uint4*)&PL[tid * 8] = *(uint4*)pl;
}

// ---------------- split-bf16 GEMM via mma.sync (legacy HMMA path) ----------------
// CTA tile: 128(M) x 64(N), K-step 64, double-buffered cp.async, SW128 xor swizzle.
// A operands: [rows][K] row-major hi/lo ; B operands: [cols][K] row-major hi/lo.
// C = A x B^T (3-term split). EPI: 0 = *mask->f32 ; 1 = +bias->f32 ;
//                                  2 = relu(+bias)->bf16 split ; 3 = dec*(1+tanh)->bf16 split
static constexpr int STAGE_BYTES = 49152;   // Ah16K + Al16K + Bh8K + Bl8K
static constexpr int GEMM_SMEM = 2 * STAGE_BYTES;

template <int EPI>
__global__ __launch_bounds__(256) void gemm_mma(
    const bf16* __restrict__ Ah, const bf16* __restrict__ Al,
    const bf16* __restrict__ Bh, const bf16* __restrict__ Bl,
    int Kd, size_t a_bs, size_t b_bs,
    const float* __restrict__ e0, size_t e0_bs, int e0_ld,
    float* __restrict__ outf, bf16* __restrict__ outh, bf16* __restrict__ outl,
    size_t o_bs, int o_ld)
{
    extern __shared__ char smem[];
    const uint32_t sb = smem_u32(smem);
    const int tid = threadIdx.x;
    const int wid = tid >> 5, lane = tid & 31;
    const int tC = blockIdx.x, tR = blockIdx.y, bz = blockIdx.z;
    const int NK = Kd >> 6;

    const bf16* A0h = Ah + (size_t)bz * a_bs + (size_t)(tR * 128) * Kd;
    const bf16* A0l = Al + (size_t)bz * a_bs + (size_t)(tR * 128) * Kd;
    const bf16* B0h = Bh + (size_t)bz * b_bs + (size_t)(tC * 64) * Kd;
    const bf16* B0l = Bl + (size_t)bz * b_bs + (size_t)(tC * 64) * Kd;

    // ---- stage loader: 3072 16B-chunks; 12 per thread
    auto load_stage = [&](int ks, int st) {
        const uint32_t base = sb + st * STAGE_BYTES;
        const int k0 = ks * 64;
        #pragma unroll
        for (int j = 0; j < 12; j++) {
            const int id = tid + j * 256;
            const bf16* src;
            uint32_t dst;
            if (id < 2048) {                    // A: hi then lo
                const int which = id >> 10;
                const int r = (id & 1023) >> 3, c = id & 7;
                src = (which ? A0l : A0h) + (size_t)r * Kd + k0 + c * 8;
                dst = base + which * 16384 + r * 128 + (((c ^ (r & 7))) << 4);
            } else {                            // B: hi then lo
                const int id2 = id - 2048;
                const int which = id2 >> 9;
                const int r = (id2 & 511) >> 3, c = id2 & 7;
                src = (which ? B0l : B0h) + (size_t)r * Kd + k0 + c * 8;
                dst = base + 32768 + which * 8192 + r * 128 + (((c ^ (r & 7))) << 4);
            }
            cp_async16(dst, src);
        }
        cp_commit();
    };

    const int m0 = (wid & 3) * 32;      // warp row offset in tile
    const int n0 = (wid >> 2) * 32;     // warp col offset in tile

    float acc[2][4][4];
    #pragma unroll
    for (int mt = 0; mt < 2; mt++)
        #pragma unroll
        for (int nt = 0; nt < 4; nt++)
            #pragma unroll
            for (int q = 0; q < 4; q++) acc[mt][nt][q] = 0.f;

    load_stage(0, 0);
    load_stage(1, 1);

    for (int ks = 0; ks < NK; ks++) {
        const int st = ks & 1;
        if (ks + 1 < NK) cp_wait<1>(); else cp_wait<0>();
        __syncthreads();

        const uint32_t base = sb + st * STAGE_BYTES;
        #pragma unroll
        for (int k16 = 0; k16 < 4; k16++) {
            const int c0 = k16 * 2;
            uint32_t ah[2][4], al[2][4], bh[4][2], bl[4][2];
            #pragma unroll
            for (int mt = 0; mt < 2; mt++) {
                const int row = m0 + mt * 16 + (lane & 15);
                const int ch = c0 + (lane >> 4);
                const uint32_t ad = base + row * 128 + ((ch ^ (row & 7)) << 4);
                ldsm_x4(ah[mt], ad);
                ldsm_x4(al[mt], ad + 16384);
            }
            #pragma unroll
            for (int hf = 0; hf < 2; hf++) {
                const int row = n0 + hf * 16 + ((lane >> 4) << 3) + (lane & 7);
                const int ch = c0 + ((lane >> 3) & 1);
                const uint32_t bd = base + 32768 + row * 128 + ((ch ^ (row & 7)) << 4);
                uint32_t t[4];
                ldsm_x4(t, bd);
                bh[hf * 2][0] = t[0]; bh[hf * 2][1] = t[1];
                bh[hf * 2 + 1][0] = t[2]; bh[hf * 2 + 1][1] = t[3];
                ldsm_x4(t, bd + 8192);
                bl[hf * 2][0] = t[0]; bl[hf * 2][1] = t[1];
                bl[hf * 2 + 1][0] = t[2]; bl[hf * 2 + 1][1] = t[3];
            }
            #pragma unroll
            for (int mt = 0; mt < 2; mt++)
                #pragma unroll
                for (int nt = 0; nt < 4; nt++) {
                    mma16816(acc[mt][nt], ah[mt], bh[nt]);
                    mma16816(acc[mt][nt], ah[mt], bl[nt]);
                    mma16816(acc[mt][nt], al[mt], bh[nt]);
                }
        }

        if (ks + 2 < NK) {
            __syncthreads();
            load_stage(ks + 2, st);
        }
    }

    // ---- epilogue: lane holds (row=l/4 [+8], col=2*(l%4) [+1]) per (mt,nt)
    const int grb = tR * 128 + m0;
    const int gcb = tC * 64 + n0;
    #pragma unroll
    for (int mt = 0; mt < 2; mt++) {
        #pragma unroll
        for (int rr = 0; rr < 2; rr++) {
            const int row = grb + mt * 16 + rr * 8 + (lane >> 2);
            #pragma unroll
            for (int nt = 0; nt < 4; nt++) {
                const int col = gcb + nt * 8 + 2 * (lane & 3);
                float v0 = acc[mt][nt][rr * 2 + 0];
                float v1 = acc[mt][nt][rr * 2 + 1];
                if (EPI == 0) {
                    const float2 mk = *(const float2*)&e0[(size_t)bz * e0_bs + (size_t)row * e0_ld + col];
                    float2 o = make_float2(v0 * mk.x, v1 * mk.y);
                    *(float2*)&outf[(size_t)bz * o_bs + (size_t)row * o_ld + col] = o;
                } else if (EPI == 1) {
                    const float2 b = *(const float2*)&e0[col];
                    float2 o = make_float2(v0 + b.x, v1 + b.y);
                    *(float2*)&outf[(size_t)bz * o_bs + (size_t)row * o_ld + col] = o;
                } else if (EPI == 2) {
                    const float2 b = *(const float2*)&e0[col];
                    float g0 = fmaxf(v0 + b.x, 0.f), g1 = fmaxf(v1 + b.y, 0.f);
                    bf16 h0 = __float2bfloat16(g0), h1 = __float2bfloat16(g1);
                    bf16 l0 = __float2bfloat16(g0 - __bfloat162float(h0));
                    bf16 l1 = __float2bfloat16(g1 - __bfloat162float(h1));
                    *(__nv_bfloat162*)&outh[(size_t)bz * o_bs + (size_t)row * o_ld + col] = __nv_bfloat162(h0, h1);
                    *(__nv_bfloat162*)&outl[(size_t)bz * o_bs + (size_t)row * o_ld + col] = __nv_bfloat162(l0, l1);
                } else {
                    const float2 dd = *(const float2*)&e0[(size_t)bz * e0_bs + (size_t)row * e0_ld + col];
                    float g0 = dd.x * (1.f + tanhf(v0));
                    float g1 = dd.y * (1.f + tanhf(v1));
                    bf16 h0 = __float2bfloat16(g0), h1 = __float2bfloat16(g1);
                    bf16 l0 = __float2bfloat16(g0 - __bfloat162float(h0));
                    bf16 l1 = __float2bfloat16(g1 - __bfloat162float(h1));
                    *(__nv_bfloat162*)&outh[(size_t)bz * o_bs + (size_t)row * o_ld + col] = __nv_bfloat162(h0, h1);
                    *(__nv_bfloat162*)&outl[(size_t)bz * o_bs + (size_t)row * o_ld + col] = __nv_bfloat162(l0, l1);
                }
            }
        }
    }
}

// ---------------- host launch ----------------
extern "C" void kernel_launch(void* const* d_in, const int* in_sizes, int n_in,
                              void* d_out, int out_size)
{
    const float* dec  = (const float*)d_in[0];
    const float* enc  = (const float*)d_in[1];
    const float* mask = (const float*)d_in[2];
    const float* Wv   = (const float*)d_in[3];
    const float* bv   = (const float*)d_in[4];
    const float* W1   = (const float*)d_in[5];
    const float* b1   = (const float*)d_in[6];
    const float* W2   = (const float*)d_in[7];
    const float* b2   = (const float*)d_in[8];
    float* out = (float*)d_out;

    float *S, *Vf;
    bf16 *Ph, *Pl, *dch, *dcl, *ech, *ecl, *VTh, *VTl, *Gh, *Gl, *Hh, *Hl;
    bf16 *WvTh, *WvTl, *W1Th, *W1Tl, *W2Th, *W2Tl;
    cudaGetSymbolAddress((void**)&S, S_buf);
    cudaGetSymbolAddress((void**)&Vf, Vf_buf);
    cudaGetSymbolAddress((void**)&Ph, Ph_buf);   cudaGetSymbolAddress((void**)&Pl, Pl_buf);
    cudaGetSymbolAddress((void**)&dch, dech_buf); cudaGetSymbolAddress((void**)&dcl, decl_buf);
    cudaGetSymbolAddress((void**)&ech, ench_buf); cudaGetSymbolAddress((void**)&ecl, encl_buf);
    cudaGetSymbolAddress((void**)&VTh, VTh_buf); cudaGetSymbolAddress((void**)&VTl, VTl_buf);
    cudaGetSymbolAddress((void**)&Gh, Gh_buf);   cudaGetSymbolAddress((void**)&Gl, Gl_buf);
    cudaGetSymbolAddress((void**)&Hh, Hh_buf);   cudaGetSymbolAddress((void**)&Hl, Hl_buf);
    cudaGetSymbolAddress((void**)&WvTh, WvTh_buf); cudaGetSymbolAddress((void**)&WvTl, WvTl_buf);
    cudaGetSymbolAddress((void**)&W1Th, W1Th_buf); cudaGetSymbolAddress((void**)&W1Tl, W1Tl_buf);
    cudaGetSymbolAddress((void**)&W2Th, W2Th_buf); cudaGetSymbolAddress((void**)&W2Tl, W2Tl_buf);

    cudaFuncSetAttribute(gemm_mma<0>, cudaFuncAttributeMaxDynamicSharedMemorySize, GEMM_SMEM);
    cudaFuncSetAttribute(gemm_mma<1>, cudaFuncAttributeMaxDynamicSharedMemorySize, GEMM_SMEM);
    cudaFuncSetAttribute(gemm_mma<2>, cudaFuncAttributeMaxDynamicSharedMemorySize, GEMM_SMEM);
    cudaFuncSetAttribute(gemm_mma<3>, cudaFuncAttributeMaxDynamicSharedMemorySize, GEMM_SMEM);

    const size_t nEmb = (size_t)Bb * Nn * Cc;       // 8M elems

    // 1) split dec/enc to bf16 hi/lo
    split_kernel<<<(unsigned)(nEmb / 4 / 256), 256>>>(dec, dch, dcl, nEmb / 4);
    split_kernel<<<(unsigned)(nEmb / 4 / 256), 256>>>(enc, ech, ecl, nEmb / 4);

    // 2) transpose+split weights: W [Cin,Cout] -> WT [Cout,Cin]
    dim3 tb(32, 8);
    transpose_split<<<dim3(Cc / 32, Cc / 32, 1), tb>>>(Wv, WvTh, WvTl, Cc, Cc, 0, 0);
    transpose_split<<<dim3(Cc / 32, Cc / 32, 1), tb>>>(W1, W1Th, W1Tl, Cc, Cc, 0, 0);
    transpose_split<<<dim3(Cc / 32, Cc / 32, 1), tb>>>(W2, W2Th, W2Tl, Cc, Cc, 0, 0);

    // 3) V = enc @ Wv + bv (fp32)   [B*M, C] x [C(out), C(in)]^T
    gemm_mma<1><<<dim3(Cc / 64, (Bb * Mm) / 128, 1), 256, GEMM_SMEM>>>(
        ech, ecl, WvTh, WvTl, Cc, 0, 0,
        bv, 0, 0, Vf, nullptr, nullptr, 0, Cc);

    // 4) VT = transpose(V) -> bf16 hi/lo  [B][C][M]
    transpose_split<<<dim3(Cc / 32, Mm / 32, Bb), tb>>>(
        Vf, VTh, VTl, Mm, Cc, (size_t)Mm * Cc, (size_t)Cc * Mm);

    // 5) S = (dec @ enc^T) * mask (fp32)
    gemm_mma<0><<<dim3(Mm / 64, Nn / 128, Bb), 256, GEMM_SMEM>>>(
        dch, dcl, ech, ecl, Cc, (size_t)Nn * Cc, (size_t)Mm * Cc,
        mask, (size_t)Nn * Mm, Mm, S, nullptr, nullptr, (size_t)Nn * Mm, Mm);

    // 6) softmax -> P hi/lo
    softmax_kernel<<<Bb * Nn, 256>>>(S, Ph, Pl);

    // 7) G = dec * (1 + tanh(P @ V)) -> bf16 hi/lo
    gemm_mma<3><<<dim3(Cc / 64, Nn / 128, Bb), 256, GEMM_SMEM>>>(
        Ph, Pl, VTh, VTl, Mm, (size_t)Nn * Mm, (size_t)Cc * Mm,
        dec, (size_t)Nn * Cc, Cc, nullptr, Gh, Gl, (size_t)Nn * Cc, Cc);

    // 8) H = relu(G @ W1 + b1) -> bf16 hi/lo
    gemm_mma<2><<<dim3(Cc / 64, (Bb * Nn) / 128, 1), 256, GEMM_SMEM>>>(
        Gh, Gl, W1Th, W1Tl, Cc, 0, 0,
        b1, 0, 0, nullptr, Hh, Hl, 0, Cc);

    // 9) out = H @ W2 + b2 (fp32)
    gemm_mma<1><<<dim3(Cc / 64, (Bb * Nn) / 128, 1), 256, GEMM_SMEM>>>(
        Hh, Hl, W2Th, W2Tl, Cc, 0, 0,
        b2, 0, 0, out, nullptr, nullptr, 0, Cc);
}

// round 4
// speedup vs baseline: 3.7878x; 1.0645x over previous
#include <cuda_runtime.h>
#include <cuda_fp16.h>
#include <cstdint>
#include <math.h>

typedef __half fp16;

static constexpr int Bb = 8, Nn = 2048, Mm = 2048, Cc = 512;

// ---------------- scratch (__device__ globals; no allocations) ----------------
__device__ float S_buf [(size_t)Bb * Nn * Mm];          // scores fp32 (128 MiB)
__device__ fp16  P_buf [(size_t)Bb * Nn * Mm];          // softmax probs (single fp16)
__device__ fp16  dech_buf[(size_t)Bb * Nn * Cc], decl_buf[(size_t)Bb * Nn * Cc];
__device__ fp16  ench_buf[(size_t)Bb * Mm * Cc], encl_buf[(size_t)Bb * Mm * Cc];
__device__ float Vf_buf [(size_t)Bb * Mm * Cc];         // enc@Wv+bv fp32
__device__ fp16  VTh_buf[(size_t)Bb * Cc * Mm], VTl_buf[(size_t)Bb * Cc * Mm];
__device__ fp16  G_buf[(size_t)Bb * Nn * Cc];           // gated, single fp16
__device__ fp16  H_buf[(size_t)Bb * Nn * Cc];           // relu(fc1), single fp16
__device__ fp16  WvT_buf[Cc * Cc];
__device__ fp16  W1Th_buf[Cc * Cc], W1Tl_buf[Cc * Cc];
__device__ fp16  W2Th_buf[Cc * Cc], W2Tl_buf[Cc * Cc];

// ---------------- arch-neutral PTX helpers ----------------
__device__ __forceinline__ uint32_t smem_u32(const void* p) {
    uint32_t a;
    asm("{ .reg .u64 t; cvta.to.shared.u64 t, %1; cvt.u32.u64 %0, t; }" : "=r"(a) : "l"(p));
    return a;
}
__device__ __forceinline__ void cp_async16(uint32_t dst, const void* src) {
    asm volatile("cp.async.cg.shared.global [%0], [%1], 16;" :: "r"(dst), "l"(src) : "memory");
}
__device__ __forceinline__ void cp_commit() { asm volatile("cp.async.commit_group;" ::: "memory"); }
template <int N> __device__ __forceinline__ void cp_wait() {
    asm volatile("cp.async.wait_group %0;" :: "n"(N) : "memory");
}
__device__ __forceinline__ void ldsm_x4(uint32_t* r, uint32_t addr) {
    asm volatile("ldmatrix.sync.aligned.m8n8.x4.shared.b16 {%0,%1,%2,%3}, [%4];"
        : "=r"(r[0]), "=r"(r[1]), "=r"(r[2]), "=r"(r[3]) : "r"(addr));
}
__device__ __forceinline__ void mma16816(float* c, const uint32_t* a, const uint32_t* b) {
    asm volatile("mma.sync.aligned.m16n8k16.row.col.f32.f16.f16.f32 "
        "{%0,%1,%2,%3}, {%4,%5,%6,%7}, {%8,%9}, {%0,%1,%2,%3};"
        : "+f"(c[0]), "+f"(c[1]), "+f"(c[2]), "+f"(c[3])
        : "r"(a[0]), "r"(a[1]), "r"(a[2]), "r"(a[3]), "r"(b[0]), "r"(b[1]));
}

// ---------------- conversion / transpose kernels ----------------
__global__ void split_kernel(const float* __restrict__ in, fp16* __restrict__ oh,
                             fp16* __restrict__ ol, size_t n4) {
    size_t i = (size_t)blockIdx.x * blockDim.x + threadIdx.x;
    if (i >= n4) return;
    float4 v = ((const float4*)in)[i];
    fp16 h0 = __float2half_rn(v.x), h1 = __float2half_rn(v.y);
    fp16 h2 = __float2half_rn(v.z), h3 = __float2half_rn(v.w);
    ((__half2*)oh)[2 * i]     = __half2(h0, h1);
    ((__half2*)oh)[2 * i + 1] = __half2(h2, h3);
    ((__half2*)ol)[2 * i] = __half2(
        __float2half_rn(v.x - __half2float(h0)), __float2half_rn(v.y - __half2float(h1)));
    ((__half2*)ol)[2 * i + 1] = __half2(
        __float2half_rn(v.z - __half2float(h2)), __float2half_rn(v.w - __half2float(h3)));
}

// out[c][r] = in[r][c]; SPLIT=1 -> hi/lo, SPLIT=0 -> single
template <int SPLIT>
__global__ void transpose_fp16(const float* __restrict__ in, fp16* __restrict__ oh,
                               fp16* __restrict__ ol, int rows, int cols,
                               size_t ibs, size_t obs) {
    __shared__ float t[32][33];
    const float* I = in + (size_t)blockIdx.z * ibs;
    fp16* OH = oh + (size_t)blockIdx.z * obs;
    fp16* OL = SPLIT ? (ol + (size_t)blockIdx.z * obs) : nullptr;
    int c0 = blockIdx.x * 32, r0 = blockIdx.y * 32;
    int tx = threadIdx.x, ty = threadIdx.y;
    #pragma unroll
    for (int k = 0; k < 4; k++)
        t[ty + 8 * k][tx] = I[(size_t)(r0 + ty + 8 * k) * cols + c0 + tx];
    __syncthreads();
    #pragma unroll
    for (int k = 0; k < 4; k++) {
        float v = t[tx][ty + 8 * k];
        size_t o = (size_t)(c0 + ty + 8 * k) * rows + r0 + tx;
        fp16 h = __float2half_rn(v);
        OH[o] = h;
        if (SPLIT) OL[o] = __float2half_rn(v - __half2float(h));
    }
}

// ---------------- nonstandard masked softmax: S fp32 -> P fp16 ----------------
__global__ __launch_bounds__(256) void softmax_kernel(const float* __restrict__ Sb,
                                                      fp16* __restrict__ Pp) {
    const float* S = Sb + (size_t)blockIdx.x * Mm;
    fp16* P = Pp + (size_t)blockIdx.x * Mm;
    const int tid = threadIdx.x;

    float4 u0 = *(const float4*)&S[tid * 8];
    float4 u1 = *(const float4*)&S[tid * 8 + 4];
    float v[8] = {u0.x, u0.y, u0.z, u0.w, u1.x, u1.y, u1.z, u1.w};

    float mx = v[0];
    #pragma unroll
    for (int i = 1; i < 8; i++) mx = fmaxf(mx, v[i]);
    #pragma unroll
    for (int o = 16; o > 0; o >>= 1) mx = fmaxf(mx, __shfl_xor_sync(0xffffffffu, mx, o));

    __shared__ float red[8];
    const int wid = tid >> 5, lid = tid & 31;
    if (lid == 0) red[wid] = mx;
    __syncthreads();
    float rmax = red[0];
    #pragma unroll
    for (int w = 1; w < 8; w++) rmax = fmaxf(rmax, red[w]);
    __syncthreads();

    float s = 0.f;
    #pragma unroll
    for (int i = 0; i < 8; i++) s += __expf(v[i] - rmax);
    #pragma unroll
    for (int o = 16; o > 0; o >>= 1) s += __shfl_xor_sync(0xffffffffu, s, o);
    if (lid == 0) red[wid] = s;
    __syncthreads();
    float tot = 0.f;
    #pragma unroll
    for (int w = 0; w < 8; w++) tot += red[w];
    const float inv = 1.f / tot;

    fp16 p[8];
    #pragma unroll
    for (int i = 0; i < 8; i++)
        p[i] = __float2half_rn((v[i] != 0.f) ? __expf(v[i] - rmax) * inv : 0.f);
    *(uint4*)&P[tid * 8] = *(uint4*)p;
}

// ---------------- split-fp16 GEMM via mma.sync ----------------
// CTA tile: 128(M) x 128(N), K-step 64, double-buffered cp.async, xor swizzle.
// A: [rows][K] hi (+lo if AS). B: [cols][K] hi (+lo if BS). C = A x B^T.
// Terms: Ah*Bh (+Ah*Bl if BS) (+Al*Bh if AS).
// EPI: 0 = *mask->f32 ; 1 = +bias->f32 ; 2 = relu(+bias)->fp16 ; 3 = dec*(1+tanh)->fp16
template <int EPI, int AS, int BS>
__global__ __launch_bounds__(256) void gemm_mma(
    const fp16* __restrict__ Ah, const fp16* __restrict__ Al,
    const fp16* __restrict__ Bh, const fp16* __restrict__ Bl,
    int Kd, size_t a_bs, size_t b_bs,
    const float* __restrict__ e0, size_t e0_bs, int e0_ld,
    float* __restrict__ outf, fp16* __restrict__ outh,
    size_t o_bs, int o_ld)
{
    constexpr int ABYTES = (1 + AS) * 16384;
    constexpr int BBYTES = (1 + BS) * 16384;
    constexpr int STAGE = ABYTES + BBYTES;

    extern __shared__ char smem[];
    const uint32_t sb = smem_u32(smem);
    const int tid = threadIdx.x;
    const int wid = tid >> 5, lane = tid & 31;
    const int tC = blockIdx.x, tR = blockIdx.y, bz = blockIdx.z;
    const int NK = Kd >> 6;

    const fp16* A0h = Ah + (size_t)bz * a_bs + (size_t)(tR * 128) * Kd;
    const fp16* A0l = AS ? (Al + (size_t)bz * a_bs + (size_t)(tR * 128) * Kd) : nullptr;
    const fp16* B0h = Bh + (size_t)bz * b_bs + (size_t)(tC * 128) * Kd;
    const fp16* B0l = BS ? (Bl + (size_t)bz * b_bs + (size_t)(tC * 128) * Kd) : nullptr;

    auto load_stage = [&](int ks, int st) {
        const uint32_t base = sb + st * STAGE;
        const int k0 = ks * 64;
        #pragma unroll
        for (int j = 0; j < 4; j++) {
            const int id = tid + j * 256;
            const int r = id >> 3, c = id & 7;
            const uint32_t sw = (uint32_t)r * 128 + (((c ^ (r & 7))) << 4);
            const size_t go = (size_t)r * Kd + k0 + c * 8;
            cp_async16(base + sw, A0h + go);
            if (AS) cp_async16(base + 16384 + sw, A0l + go);
            cp_async16(base + ABYTES + sw, B0h + go);
            if (BS) cp_async16(base + ABYTES + 16384 + sw, B0l + go);
        }
        cp_commit();
    };

    const int m0 = (wid & 3) * 32;      // warp row offset
    const int n0 = (wid >> 2) * 64;     // warp col offset

    float acc[2][8][4];
    #pragma unroll
    for (int mt = 0; mt < 2; mt++)
        #pragma unroll
        for (int nt = 0; nt < 8; nt++)
            #pragma unroll
            for (int q = 0; q < 4; q++) acc[mt][nt][q] = 0.f;

    load_stage(0, 0);
    load_stage(1, 1);

    for (int ks = 0; ks < NK; ks++) {
        const int st = ks & 1;
        if (ks + 1 < NK) cp_wait<1>(); else cp_wait<0>();
        __syncthreads();

        const uint32_t base = sb + st * STAGE;
        #pragma unroll
        for (int k16 = 0; k16 < 4; k16++) {
            const int c0 = k16 * 2;
            uint32_t ah[2][4], al[2][4], bh[8][2], bl[8][2];
            #pragma unroll
            for (int mt = 0; mt < 2; mt++) {
                const int row = m0 + mt * 16 + (lane & 15);
                const int ch = c0 + (lane >> 4);
                const uint32_t ad = base + row * 128 + ((ch ^ (row & 7)) << 4);
                ldsm_x4(ah[mt], ad);
                if (AS) ldsm_x4(al[mt], ad + 16384);
            }
            #pragma unroll
            for (int g = 0; g < 4; g++) {
                const int row = n0 + g * 16 + ((lane >> 4) << 3) + (lane & 7);
                const int ch = c0 + ((lane >> 3) & 1);
                const uint32_t bd = base + ABYTES + row * 128 + ((ch ^ (row & 7)) << 4);
                uint32_t t[4];
                ldsm_x4(t, bd);
                bh[g * 2][0] = t[0]; bh[g * 2][1] = t[1];
                bh[g * 2 + 1][0] = t[2]; bh[g * 2 + 1][1] = t[3];
                if (BS) {
                    ldsm_x4(t, bd + 16384);
                    bl[g * 2][0] = t[0]; bl[g * 2][1] = t[1];
                    bl[g * 2 + 1][0] = t[2]; bl[g * 2 + 1][1] = t[3];
                }
            }
            #pragma unroll
            for (int mt = 0; mt < 2; mt++)
                #pragma unroll
                for (int nt = 0; nt < 8; nt++) {
                    mma16816(acc[mt][nt], ah[mt], bh[nt]);
                    if (BS) mma16816(acc[mt][nt], ah[mt], bl[nt]);
                    if (AS) mma16816(acc[mt][nt], al[mt], bh[nt]);
                }
        }

        if (ks + 2 < NK) {
            __syncthreads();
            load_stage(ks + 2, st);
        }
    }

    // ---- epilogue
    const int grb = tR * 128 + m0;
    const int gcb = tC * 128 + n0;
    #pragma unroll
    for (int mt = 0; mt < 2; mt++) {
        #pragma unroll
        for (int rr = 0; rr < 2; rr++) {
            const int row = grb + mt * 16 + rr * 8 + (lane >> 2);
            #pragma unroll
            for (int nt = 0; nt < 8; nt++) {
                const int col = gcb + nt * 8 + 2 * (lane & 3);
                float v0 = acc[mt][nt][rr * 2 + 0];
                float v1 = acc[mt][nt][rr * 2 + 1];
                if (EPI == 0) {
                    const float2 mk = *(const float2*)&e0[(size_t)bz * e0_bs + (size_t)row * e0_ld + col];
                    *(float2*)&outf[(size_t)bz * o_bs + (size_t)row * o_ld + col] =
                        make_float2(v0 * mk.x, v1 * mk.y);
                } else if (EPI == 1) {
                    const float2 b = *(const float2*)&e0[col];
                    *(float2*)&outf[(size_t)bz * o_bs + (size_t)row * o_ld + col] =
                        make_float2(v0 + b.x, v1 + b.y);
                } else if (EPI == 2) {
                    const float2 b = *(const float2*)&e0[col];
                    float g0 = fmaxf(v0 + b.x, 0.f), g1 = fmaxf(v1 + b.y, 0.f);
                    *(__half2*)&outh[(size_t)bz * o_bs + (size_t)row * o_ld + col] =
                        __half2(__float2half_rn(g0), __float2half_rn(g1));
                } else {
                    const float2 dd = *(const float2*)&e0[(size_t)bz * e0_bs + (size_t)row * e0_ld + col];
                    float g0 = dd.x * (1.f + tanhf(v0));
                    float g1 = dd.y * (1.f + tanhf(v1));
                    *(__half2*)&outh[(size_t)bz * o_bs + (size_t)row * o_ld + col] =
                        __half2(__float2half_rn(g0), __float2half_rn(g1));
                }
            }
        }
    }
}

// ---------------- host launch ----------------
extern "C" void kernel_launch(void* const* d_in, const int* in_sizes, int n_in,
                              void* d_out, int out_size)
{
    const float* dec  = (const float*)d_in[0];
    const float* enc  = (const float*)d_in[1];
    const float* mask = (const float*)d_in[2];
    const float* Wv   = (const float*)d_in[3];
    const float* bv   = (const float*)d_in[4];
    const float* W1   = (const float*)d_in[5];
    const float* b1   = (const float*)d_in[6];
    const float* W2   = (const float*)d_in[7];
    const float* b2   = (const float*)d_in[8];
    float* out = (float*)d_out;

    float *S, *Vf;
    fp16 *P, *dch, *dcl, *ech, *ecl, *VTh, *VTl, *G, *H;
    fp16 *WvT, *W1Th, *W1Tl, *W2Th, *W2Tl;
    cudaGetSymbolAddress((void**)&S, S_buf);
    cudaGetSymbolAddress((void**)&Vf, Vf_buf);
    cudaGetSymbolAddress((void**)&P, P_buf);
    cudaGetSymbolAddress((void**)&dch, dech_buf); cudaGetSymbolAddress((void**)&dcl, decl_buf);
    cudaGetSymbolAddress((void**)&ech, ench_buf); cudaGetSymbolAddress((void**)&ecl, encl_buf);
    cudaGetSymbolAddress((void**)&VTh, VTh_buf); cudaGetSymbolAddress((void**)&VTl, VTl_buf);
    cudaGetSymbolAddress((void**)&G, G_buf);     cudaGetSymbolAddress((void**)&H, H_buf);
    cudaGetSymbolAddress((void**)&WvT, WvT_buf);
    cudaGetSymbolAddress((void**)&W1Th, W1Th_buf); cudaGetSymbolAddress((void**)&W1Tl, W1Tl_buf);
    cudaGetSymbolAddress((void**)&W2Th, W2Th_buf); cudaGetSymbolAddress((void**)&W2Tl, W2Tl_buf);

    // smem sizes per variant
    constexpr int SM_3T = 2 * (2 * 16384 + 2 * 16384);   // 128 KB (AS=1,BS=1)
    constexpr int SM_A  = 2 * (2 * 16384 + 1 * 16384);   // 96 KB  (AS=1,BS=0)
    constexpr int SM_B  = 2 * (1 * 16384 + 2 * 16384);   // 96 KB  (AS=0,BS=1)
    cudaFuncSetAttribute(gemm_mma<0,1,1>, cudaFuncAttributeMaxDynamicSharedMemorySize, SM_3T);
    cudaFuncSetAttribute(gemm_mma<1,1,0>, cudaFuncAttributeMaxDynamicSharedMemorySize, SM_A);
    cudaFuncSetAttribute(gemm_mma<3,0,1>, cudaFuncAttributeMaxDynamicSharedMemorySize, SM_B);
    cudaFuncSetAttribute(gemm_mma<2,0,1>, cudaFuncAttributeMaxDynamicSharedMemorySize, SM_B);
    cudaFuncSetAttribute(gemm_mma<1,0,1>, cudaFuncAttributeMaxDynamicSharedMemorySize, SM_B);

    const size_t nEmb = (size_t)Bb * Nn * Cc;       // 8M elems

    // 1) split dec/enc to fp16 hi/lo
    split_kernel<<<(unsigned)(nEmb / 4 / 256), 256>>>(dec, dch, dcl, nEmb / 4);
    split_kernel<<<(unsigned)(nEmb / 4 / 256), 256>>>(enc, ech, ecl, nEmb / 4);

    // 2) weight transposes: WvT single; W1T/W2T hi/lo
    dim3 tb(32, 8);
    transpose_fp16<0><<<dim3(Cc / 32, Cc / 32, 1), tb>>>(Wv, WvT, nullptr, Cc, Cc, 0, 0);
    transpose_fp16<1><<<dim3(Cc / 32, Cc / 32, 1), tb>>>(W1, W1Th, W1Tl, Cc, Cc, 0, 0);
    transpose_fp16<1><<<dim3(Cc / 32, Cc / 32, 1), tb>>>(W2, W2Th, W2Tl, Cc, Cc, 0, 0);

    // 3) Vf = enc @ Wv + bv (fp32): A=enc split, B=WvT single
    gemm_mma<1,1,0><<<dim3(Cc / 128, (Bb * Mm) / 128, 1), 256, SM_A>>>(
        ech, ecl, WvT, nullptr, Cc, 0, 0,
        bv, 0, 0, Vf, nullptr, 0, Cc);

    // 4) VT = transpose(Vf) -> fp16 hi/lo  [B][C][M]
    transpose_fp16<1><<<dim3(Cc / 32, Mm / 32, Bb), tb>>>(
        Vf, VTh, VTl, Mm, Cc, (size_t)Mm * Cc, (size_t)Cc * Mm);

    // 5) S = (dec @ enc^T) * mask (fp32): 3-term
    gemm_mma<0,1,1><<<dim3(Mm / 128, Nn / 128, Bb), 256, SM_3T>>>(
        dch, dcl, ech, ecl, Cc, (size_t)Nn * Cc, (size_t)Mm * Cc,
        mask, (size_t)Nn * Mm, Mm, S, nullptr, (size_t)Nn * Mm, Mm);

    // 6) softmax -> P fp16 single
    softmax_kernel<<<Bb * Nn, 256>>>(S, P);

    // 7) G = dec * (1 + tanh(P @ V)) -> fp16: A=P single, B=VT split
    gemm_mma<3,0,1><<<dim3(Cc / 128, Nn / 128, Bb), 256, SM_B>>>(
        P, nullptr, VTh, VTl, Mm, (size_t)Nn * Mm, (size_t)Cc * Mm,
        dec, (size_t)Nn * Cc, Cc, nullptr, G, (size_t)Nn * Cc, Cc);

    // 8) H = relu(G @ W1 + b1) -> fp16: A=G single, B=W1T split
    gemm_mma<2,0,1><<<dim3(Cc / 128, (Bb * Nn) / 128, 1), 256, SM_B>>>(
        G, nullptr, W1Th, W1Tl, Cc, 0, 0,
        b1, 0, 0, nullptr, H, 0, Cc);

    // 9) out = H @ W2 + b2 (fp32): A=H single, B=W2T split
    gemm_mma<1,0,1><<<dim3(Cc / 128, (Bb * Nn) / 128, 1), 256, SM_B>>>(
        H, nullptr, W2Th, W2Tl, Cc, 0, 0,
        b2, 0, 0, out, nullptr, 0, Cc);
}

// round 5
// speedup vs baseline: 3.9297x; 1.0374x over previous
#include <cuda_runtime.h>
#include <cuda_fp16.h>
#include <cstdint>
#include <math.h>

typedef __half fp16;

static constexpr int Bb = 8, Nn = 2048, Mm = 2048, Cc = 512;

// ---------------- scratch (__device__ globals; no allocations) ----------------
__device__ float S_buf [(size_t)Bb * Nn * Mm];          // scores fp32 (128 MiB)
__device__ fp16  P_buf [(size_t)Bb * Nn * Mm];          // softmax probs (single fp16)
__device__ fp16  dech_buf[(size_t)Bb * Nn * Cc], decl_buf[(size_t)Bb * Nn * Cc];
__device__ fp16  ench_buf[(size_t)Bb * Mm * Cc], encl_buf[(size_t)Bb * Mm * Cc];
__device__ float Vf_buf [(size_t)Bb * Mm * Cc];         // enc@Wv+bv fp32
__device__ fp16  VTh_buf[(size_t)Bb * Cc * Mm], VTl_buf[(size_t)Bb * Cc * Mm];
__device__ fp16  G_buf[(size_t)Bb * Nn * Cc];           // gated, single fp16
__device__ fp16  H_buf[(size_t)Bb * Nn * Cc];           // relu(fc1), single fp16
__device__ fp16  WvT_buf[Cc * Cc];
__device__ fp16  W1Th_buf[Cc * Cc], W1Tl_buf[Cc * Cc];
__device__ fp16  W2Th_buf[Cc * Cc], W2Tl_buf[Cc * Cc];

// ---------------- arch-neutral PTX helpers ----------------
__device__ __forceinline__ uint32_t smem_u32(const void* p) {
    uint32_t a;
    asm("{ .reg .u64 t; cvta.to.shared.u64 t, %1; cvt.u32.u64 %0, t; }" : "=r"(a) : "l"(p));
    return a;
}
__device__ __forceinline__ void cp_async16(uint32_t dst, const void* src) {
    asm volatile("cp.async.cg.shared.global [%0], [%1], 16;" :: "r"(dst), "l"(src) : "memory");
}
__device__ __forceinline__ void cp_commit() { asm volatile("cp.async.commit_group;" ::: "memory"); }
template <int N> __device__ __forceinline__ void cp_wait() {
    asm volatile("cp.async.wait_group %0;" :: "n"(N) : "memory");
}
__device__ __forceinline__ void ldsm_x4(uint32_t* r, uint32_t addr) {
    asm volatile("ldmatrix.sync.aligned.m8n8.x4.shared.b16 {%0,%1,%2,%3}, [%4];"
        : "=r"(r[0]), "=r"(r[1]), "=r"(r[2]), "=r"(r[3]) : "r"(addr));
}
__device__ __forceinline__ void mma16816(float* c, const uint32_t* a, const uint32_t* b) {
    asm volatile("mma.sync.aligned.m16n8k16.row.col.f32.f16.f16.f32 "
        "{%0,%1,%2,%3}, {%4,%5,%6,%7}, {%8,%9}, {%0,%1,%2,%3};"
        : "+f"(c[0]), "+f"(c[1]), "+f"(c[2]), "+f"(c[3])
        : "r"(a[0]), "r"(a[1]), "r"(a[2]), "r"(a[3]), "r"(b[0]), "r"(b[1]));
}
// 64B-row swizzle: logical chunk c (0..3) of row r -> phys chunk c ^ ((r>>1)&3)
__device__ __forceinline__ uint32_t sw64(int r, int c) {
    return (uint32_t)r * 64u + (uint32_t)((c ^ ((r >> 1) & 3)) << 4);
}

// ---------------- conversion / transpose kernels ----------------
// grid.y = 0 -> (inA -> ohA/olA), 1 -> (inB -> ohB/olB)
__global__ void split2_kernel(const float* __restrict__ inA, fp16* __restrict__ ohA, fp16* __restrict__ olA,
                              const float* __restrict__ inB, fp16* __restrict__ ohB, fp16* __restrict__ olB,
                              size_t n4) {
    size_t i = (size_t)blockIdx.x * blockDim.x + threadIdx.x;
    if (i >= n4) return;
    const float* in = blockIdx.y ? inB : inA;
    fp16* oh = blockIdx.y ? ohB : ohA;
    fp16* ol = blockIdx.y ? olB : olA;
    float4 v = ((const float4*)in)[i];
    fp16 h0 = __float2half_rn(v.x), h1 = __float2half_rn(v.y);
    fp16 h2 = __float2half_rn(v.z), h3 = __float2half_rn(v.w);
    ((__half2*)oh)[2 * i]     = __half2(h0, h1);
    ((__half2*)oh)[2 * i + 1] = __half2(h2, h3);
    ((__half2*)ol)[2 * i] = __half2(
        __float2half_rn(v.x - __half2float(h0)), __float2half_rn(v.y - __half2float(h1)));
    ((__half2*)ol)[2 * i + 1] = __half2(
        __float2half_rn(v.z - __half2float(h2)), __float2half_rn(v.w - __half2float(h3)));
}

// out[c][r] = in[r][c]; SPLIT=1 -> hi/lo, SPLIT=0 -> single
template <int SPLIT>
__global__ void transpose_fp16(const float* __restrict__ in, fp16* __restrict__ oh,
                               fp16* __restrict__ ol, int rows, int cols,
                               size_t ibs, size_t obs) {
    __shared__ float t[32][33];
    const float* I = in + (size_t)blockIdx.z * ibs;
    fp16* OH = oh + (size_t)blockIdx.z * obs;
    fp16* OL = SPLIT ? (ol + (size_t)blockIdx.z * obs) : nullptr;
    int c0 = blockIdx.x * 32, r0 = blockIdx.y * 32;
    int tx = threadIdx.x, ty = threadIdx.y;
    #pragma unroll
    for (int k = 0; k < 4; k++)
        t[ty + 8 * k][tx] = I[(size_t)(r0 + ty + 8 * k) * cols + c0 + tx];
    __syncthreads();
    #pragma unroll
    for (int k = 0; k < 4; k++) {
        float v = t[tx][ty + 8 * k];
        size_t o = (size_t)(c0 + ty + 8 * k) * rows + r0 + tx;
        fp16 h = __float2half_rn(v);
        OH[o] = h;
        if (SPLIT) OL[o] = __float2half_rn(v - __half2float(h));
    }
}

// ---------------- nonstandard masked softmax: S fp32 -> P fp16 ----------------
__global__ __launch_bounds__(256) void softmax_kernel(const float* __restrict__ Sb,
                                                      fp16* __restrict__ Pp) {
    const float* S = Sb + (size_t)blockIdx.x * Mm;
    fp16* P = Pp + (size_t)blockIdx.x * Mm;
    const int tid = threadIdx.x;

    float4 u0 = *(const float4*)&S[tid * 8];
    float4 u1 = *(const float4*)&S[tid * 8 + 4];
    float v[8] = {u0.x, u0.y, u0.z, u0.w, u1.x, u1.y, u1.z, u1.w};

    float mx = v[0];
    #pragma unroll
    for (int i = 1; i < 8; i++) mx = fmaxf(mx, v[i]);
    #pragma unroll
    for (int o = 16; o > 0; o >>= 1) mx = fmaxf(mx, __shfl_xor_sync(0xffffffffu, mx, o));

    __shared__ float red[8];
    const int wid = tid >> 5, lid = tid & 31;
    if (lid == 0) red[wid] = mx;
    __syncthreads();
    float rmax = red[0];
    #pragma unroll
    for (int w = 1; w < 8; w++) rmax = fmaxf(rmax, red[w]);
    __syncthreads();

    float e[8];
    float s = 0.f;
    #pragma unroll
    for (int i = 0; i < 8; i++) { e[i] = __expf(v[i] - rmax); s += e[i]; }
    #pragma unroll
    for (int o = 16; o > 0; o >>= 1) s += __shfl_xor_sync(0xffffffffu, s, o);
    if (lid == 0) red[wid] = s;
    __syncthreads();
    float tot = 0.f;
    #pragma unroll
    for (int w = 0; w < 8; w++) tot += red[w];
    const float inv = 1.f / tot;

    fp16 p[8];
    #pragma unroll
    for (int i = 0; i < 8; i++)
        p[i] = __float2half_rn((v[i] != 0.f) ? e[i] * inv : 0.f);
    *(uint4*)&P[tid * 8] = *(uint4*)p;
}

// ---------------- split-fp16 GEMM via mma.sync ----------------
// CTA tile: 128(M) x 64(N), K-step 32, 3-stage cp.async pipeline, 64B-row swizzle.
// A: [rows][K] hi (+lo if AS). B: [cols][K] hi (+lo if BS). C = A x B^T.
// Terms: Ah*Bh (+Ah*Bl if BS) (+Al*Bh if AS).
// EPI: 0 = *mask->f32 ; 1 = +bias->f32 ; 2 = relu(+bias)->fp16 ; 3 = dec*(1+tanh)->fp16
template <int EPI, int AS, int BS>
__global__ __launch_bounds__(256) void gemm_mma(
    const fp16* __restrict__ Ah, const fp16* __restrict__ Al,
    const fp16* __restrict__ Bh, const fp16* __restrict__ Bl,
    int Kd, size_t a_bs, size_t b_bs,
    const float* __restrict__ e0, size_t e0_bs, int e0_ld,
    float* __restrict__ outf, fp16* __restrict__ outh,
    size_t o_bs, int o_ld)
{
    constexpr int ACOMP = 8192;                    // 128 rows x 64 B
    constexpr int BCOMP = 4096;                    // 64 rows x 64 B
    constexpr int ABYTES = (1 + AS) * ACOMP;
    constexpr int STAGE = ABYTES + (1 + BS) * BCOMP;

    extern __shared__ char smem[];
    const uint32_t sb = smem_u32(smem);
    const int tid = threadIdx.x;
    const int wid = tid >> 5, lane = tid & 31;
    const int tC = blockIdx.x, tR = blockIdx.y, bz = blockIdx.z;
    const int NK = Kd >> 5;

    const fp16* A0h = Ah + (size_t)bz * a_bs + (size_t)(tR * 128) * Kd;
    const fp16* A0l = AS ? (Al + (size_t)bz * a_bs + (size_t)(tR * 128) * Kd) : nullptr;
    const fp16* B0h = Bh + (size_t)bz * b_bs + (size_t)(tC * 64) * Kd;
    const fp16* B0l = BS ? (Bl + (size_t)bz * b_bs + (size_t)(tC * 64) * Kd) : nullptr;

    auto load_stage = [&](int ks, int st) {
        const uint32_t base = sb + st * STAGE;
        const int k0 = ks * 32;
        // A components: 512 chunks each -> 2 per thread
        #pragma unroll
        for (int j = 0; j < 2; j++) {
            const int id = tid + j * 256;
            const int r = id >> 2, c = id & 3;
            const size_t go = (size_t)r * Kd + k0 + c * 8;
            const uint32_t sw = sw64(r, c);
            cp_async16(base + sw, A0h + go);
            if (AS) cp_async16(base + ACOMP + sw, A0l + go);
        }
        // B components: 256 chunks each -> 1 per thread
        {
            const int r = tid >> 2, c = tid & 3;
            const size_t go = (size_t)r * Kd + k0 + c * 8;
            const uint32_t sw = sw64(r, c);
            cp_async16(base + ABYTES + sw, B0h + go);
            if (BS) cp_async16(base + ABYTES + BCOMP + sw, B0l + go);
        }
        cp_commit();
    };

    const int m0 = (wid & 3) * 32;      // warp row offset (4 warps over 128 rows)
    const int n0 = (wid >> 2) * 32;     // warp col offset (2 warps over 64 cols)

    float acc[2][4][4];
    #pragma unroll
    for (int mt = 0; mt < 2; mt++)
        #pragma unroll
        for (int nt = 0; nt < 4; nt++)
            #pragma unroll
            for (int q = 0; q < 4; q++) acc[mt][nt][q] = 0.f;

    load_stage(0, 0);
    load_stage(1, 1);

    for (int ks = 0; ks < NK; ks++) {
        if (ks + 1 < NK) cp_wait<1>(); else cp_wait<0>();
        __syncthreads();
        if (ks + 2 < NK) load_stage(ks + 2, (ks + 2) % 3);

        const uint32_t base = sb + (ks % 3) * STAGE;
        #pragma unroll
        for (int kk = 0; kk < 2; kk++) {
            const int c0 = kk * 2;
            uint32_t ah[2][4], al[2][4], bh[4][2], bl[4][2];
            #pragma unroll
            for (int mt = 0; mt < 2; mt++) {
                const int row = m0 + mt * 16 + (lane & 15);
                const int ch = c0 + (lane >> 4);
                const uint32_t ad = base + sw64(row, ch);
                ldsm_x4(ah[mt], ad);
                if (AS) ldsm_x4(al[mt], ad + ACOMP);
            }
            #pragma unroll
            for (int g = 0; g < 2; g++) {
                const int row = n0 + g * 16 + ((lane >> 4) << 3) + (lane & 7);
                const int ch = c0 + ((lane >> 3) & 1);
                const uint32_t bd = base + ABYTES + sw64(row, ch);
                uint32_t t[4];
                ldsm_x4(t, bd);
                bh[g * 2][0] = t[0]; bh[g * 2][1] = t[1];
                bh[g * 2 + 1][0] = t[2]; bh[g * 2 + 1][1] = t[3];
                if (BS) {
                    ldsm_x4(t, bd + BCOMP);
                    bl[g * 2][0] = t[0]; bl[g * 2][1] = t[1];
                    bl[g * 2 + 1][0] = t[2]; bl[g * 2 + 1][1] = t[3];
                }
            }
            #pragma unroll
            for (int mt = 0; mt < 2; mt++)
                #pragma unroll
                for (int nt = 0; nt < 4; nt++) {
                    mma16816(acc[mt][nt], ah[mt], bh[nt]);
                    if (BS) mma16816(acc[mt][nt], ah[mt], bl[nt]);
                    if (AS) mma16816(acc[mt][nt], al[mt], bh[nt]);
                }
        }
    }

    // ---- epilogue
    const int grb = tR * 128 + m0;
    const int gcb = tC * 64 + n0;
    #pragma unroll
    for (int mt = 0; mt < 2; mt++) {
        #pragma unroll
        for (int rr = 0; rr < 2; rr++) {
            const int row = grb + mt * 16 + rr * 8 + (lane >> 2);
            #pragma unroll
            for (int nt = 0; nt < 4; nt++) {
                const int col = gcb + nt * 8 + 2 * (lane & 3);
                float v0 = acc[mt][nt][rr * 2 + 0];
                float v1 = acc[mt][nt][rr * 2 + 1];
                if (EPI == 0) {
                    const float2 mk = *(const float2*)&e0[(size_t)bz * e0_bs + (size_t)row * e0_ld + col];
                    *(float2*)&outf[(size_t)bz * o_bs + (size_t)row * o_ld + col] =
                        make_float2(v0 * mk.x, v1 * mk.y);
                } else if (EPI == 1) {
                    const float2 b = *(const float2*)&e0[col];
                    *(float2*)&outf[(size_t)bz * o_bs + (size_t)row * o_ld + col] =
                        make_float2(v0 + b.x, v1 + b.y);
                } else if (EPI == 2) {
                    const float2 b = *(const float2*)&e0[col];
                    float g0 = fmaxf(v0 + b.x, 0.f), g1 = fmaxf(v1 + b.y, 0.f);
                    *(__half2*)&outh[(size_t)bz * o_bs + (size_t)row * o_ld + col] =
                        __half2(__float2half_rn(g0), __float2half_rn(g1));
                } else {
                    const float2 dd = *(const float2*)&e0[(size_t)bz * e0_bs + (size_t)row * e0_ld + col];
                    float g0 = dd.x * (1.f + tanhf(v0));
                    float g1 = dd.y * (1.f + tanhf(v1));
                    *(__half2*)&outh[(size_t)bz * o_bs + (size_t)row * o_ld + col] =
                        __half2(__float2half_rn(g0), __float2half_rn(g1));
                }
            }
        }
    }
}

// ---------------- host launch ----------------
extern "C" void kernel_launch(void* const* d_in, const int* in_sizes, int n_in,
                              void* d_out, int out_size)
{
    const float* dec  = (const float*)d_in[0];
    const float* enc  = (const float*)d_in[1];
    const float* mask = (const float*)d_in[2];
    const float* Wv   = (const float*)d_in[3];
    const float* bv   = (const float*)d_in[4];
    const float* W1   = (const float*)d_in[5];
    const float* b1   = (const float*)d_in[6];
    const float* W2   = (const float*)d_in[7];
    const float* b2   = (const float*)d_in[8];
    float* out = (float*)d_out;

    float *S, *Vf;
    fp16 *P, *dch, *dcl, *ech, *ecl, *VTh, *VTl, *G, *H;
    fp16 *WvT, *W1Th, *W1Tl, *W2Th, *W2Tl;
    cudaGetSymbolAddress((void**)&S, S_buf);
    cudaGetSymbolAddress((void**)&Vf, Vf_buf);
    cudaGetSymbolAddress((void**)&P, P_buf);
    cudaGetSymbolAddress((void**)&dch, dech_buf); cudaGetSymbolAddress((void**)&dcl, decl_buf);
    cudaGetSymbolAddress((void**)&ech, ench_buf); cudaGetSymbolAddress((void**)&ecl, encl_buf);
    cudaGetSymbolAddress((void**)&VTh, VTh_buf); cudaGetSymbolAddress((void**)&VTl, VTl_buf);
    cudaGetSymbolAddress((void**)&G, G_buf);     cudaGetSymbolAddress((void**)&H, H_buf);
    cudaGetSymbolAddress((void**)&WvT, WvT_buf);
    cudaGetSymbolAddress((void**)&W1Th, W1Th_buf); cudaGetSymbolAddress((void**)&W1Tl, W1Tl_buf);
    cudaGetSymbolAddress((void**)&W2Th, W2Th_buf); cudaGetSymbolAddress((void**)&W2Tl, W2Tl_buf);

    // 3-stage smem footprints
    constexpr int SM_3T = 3 * (2 * 8192 + 2 * 4096);   // 73728 (AS=1,BS=1)
    constexpr int SM_A  = 3 * (2 * 8192 + 1 * 4096);   // 61440 (AS=1,BS=0)
    constexpr int SM_B  = 3 * (1 * 8192 + 2 * 4096);   // 49152 (AS=0,BS=1)
    cudaFuncSetAttribute(gemm_mma<0,1,1>, cudaFuncAttributeMaxDynamicSharedMemorySize, SM_3T);
    cudaFuncSetAttribute(gemm_mma<1,1,0>, cudaFuncAttributeMaxDynamicSharedMemorySize, SM_A);
    cudaFuncSetAttribute(gemm_mma<3,0,1>, cudaFuncAttributeMaxDynamicSharedMemorySize, SM_B);
    cudaFuncSetAttribute(gemm_mma<2,0,1>, cudaFuncAttributeMaxDynamicSharedMemorySize, SM_B);
    cudaFuncSetAttribute(gemm_mma<1,0,1>, cudaFuncAttributeMaxDynamicSharedMemorySize, SM_B);

    const size_t nEmb = (size_t)Bb * Nn * Cc;       // 8M elems

    // 1) split dec & enc to fp16 hi/lo (one launch)
    split2_kernel<<<dim3((unsigned)(nEmb / 4 / 256), 2), 256>>>(
        dec, dch, dcl, enc, ech, ecl, nEmb / 4);

    // 2) weight transposes: WvT single; W1T/W2T hi/lo
    dim3 tb(32, 8);
    transpose_fp16<0><<<dim3(Cc / 32, Cc / 32, 1), tb>>>(Wv, WvT, nullptr, Cc, Cc, 0, 0);
    transpose_fp16<1><<<dim3(Cc / 32, Cc / 32, 1), tb>>>(W1, W1Th, W1Tl, Cc, Cc, 0, 0);
    transpose_fp16<1><<<dim3(Cc / 32, Cc / 32, 1), tb>>>(W2, W2Th, W2Tl, Cc, Cc, 0, 0);

    // 3) Vf = enc @ Wv + bv (fp32): A=enc split, B=WvT single
    gemm_mma<1,1,0><<<dim3(Cc / 64, (Bb * Mm) / 128, 1), 256, SM_A>>>(
        ech, ecl, WvT, nullptr, Cc, 0, 0,
        bv, 0, 0, Vf, nullptr, 0, Cc);

    // 4) VT = transpose(Vf) -> fp16 hi/lo  [B][C][M]
    transpose_fp16<1><<<dim3(Cc / 32, Mm / 32, Bb), tb>>>(
        Vf, VTh, VTl, Mm, Cc, (size_t)Mm * Cc, (size_t)Cc * Mm);

    // 5) S = (dec @ enc^T) * mask (fp32): 3-term
    gemm_mma<0,1,1><<<dim3(Mm / 64, Nn / 128, Bb), 256, SM_3T>>>(
        dch, dcl, ech, ecl, Cc, (size_t)Nn * Cc, (size_t)Mm * Cc,
        mask, (size_t)Nn * Mm, Mm, S, nullptr, (size_t)Nn * Mm, Mm);

    // 6) softmax -> P fp16 single
    softmax_kernel<<<Bb * Nn, 256>>>(S, P);

    // 7) G = dec * (1 + tanh(P @ V)) -> fp16: A=P single, B=VT split
    gemm_mma<3,0,1><<<dim3(Cc / 64, Nn / 128, Bb), 256, SM_B>>>(
        P, nullptr, VTh, VTl, Mm, (size_t)Nn * Mm, (size_t)Cc * Mm,
        dec, (size_t)Nn * Cc, Cc, nullptr, G, (size_t)Nn * Cc, Cc);

    // 8) H = relu(G @ W1 + b1) -> fp16: A=G single, B=W1T split
    gemm_mma<2,0,1><<<dim3(Cc / 64, (Bb * Nn) / 128, 1), 256, SM_B>>>(
        G, nullptr, W1Th, W1Tl, Cc, 0, 0,
        b1, 0, 0, nullptr, H, 0, Cc);

    // 9) out = H @ W2 + b2 (fp32): A=H single, B=W2T split
    gemm_mma<1,0,1><<<dim3(Cc / 64, (Bb * Nn) / 128, 1), 256, SM_B>>>(
        H, nullptr, W2Th, W2Tl, Cc, 0, 0,
        b2, 0, 0, out, nullptr, 0, Cc);
}

// round 6
// speedup vs baseline: 4.6928x; 1.1942x over previous
#include <cuda_runtime.h>
#include <cuda_fp16.h>
#include <cstdint>
#include <math.h>

typedef __half fp16;

static constexpr int Bb = 8, Nn = 2048, Mm = 2048, Cc = 512;

// ---------------- scratch (__device__ globals; no allocations) ----------------
__device__ float S_buf [(size_t)Bb * Nn * Mm];          // scores fp32 (128 MiB)
__device__ fp16  P_buf [(size_t)Bb * Nn * Mm];          // softmax probs (single fp16)
__device__ fp16  dech_buf[(size_t)Bb * Nn * Cc], decl_buf[(size_t)Bb * Nn * Cc];
__device__ fp16  ench_buf[(size_t)Bb * Mm * Cc], encl_buf[(size_t)Bb * Mm * Cc];
__device__ float Vf_buf [(size_t)Bb * Mm * Cc];         // enc@Wv+bv fp32
__device__ fp16  VT_buf [(size_t)Bb * Cc * Mm];         // V^T single fp16
__device__ fp16  G_buf[(size_t)Bb * Nn * Cc];           // gated, single fp16
__device__ fp16  H_buf[(size_t)Bb * Nn * Cc];           // relu(fc1), single fp16
__device__ fp16  WvT_buf[Cc * Cc];
__device__ fp16  W1T_buf[Cc * Cc];
__device__ fp16  W2T_buf[Cc * Cc];

// ---------------- arch-neutral PTX helpers ----------------
__device__ __forceinline__ uint32_t smem_u32(const void* p) {
    uint32_t a;
    asm("{ .reg .u64 t; cvta.to.shared.u64 t, %1; cvt.u32.u64 %0, t; }" : "=r"(a) : "l"(p));
    return a;
}
__device__ __forceinline__ void cp_async16(uint32_t dst, const void* src) {
    asm volatile("cp.async.cg.shared.global [%0], [%1], 16;" :: "r"(dst), "l"(src) : "memory");
}
__device__ __forceinline__ void cp_commit() { asm volatile("cp.async.commit_group;" ::: "memory"); }
template <int N> __device__ __forceinline__ void cp_wait() {
    asm volatile("cp.async.wait_group %0;" :: "n"(N) : "memory");
}
__device__ __forceinline__ void ldsm_x4(uint32_t* r, uint32_t addr) {
    asm volatile("ldmatrix.sync.aligned.m8n8.x4.shared.b16 {%0,%1,%2,%3}, [%4];"
        : "=r"(r[0]), "=r"(r[1]), "=r"(r[2]), "=r"(r[3]) : "r"(addr));
}
__device__ __forceinline__ void mma16816(float* c, const uint32_t* a, const uint32_t* b) {
    asm volatile("mma.sync.aligned.m16n8k16.row.col.f32.f16.f16.f32 "
        "{%0,%1,%2,%3}, {%4,%5,%6,%7}, {%8,%9}, {%0,%1,%2,%3};"
        : "+f"(c[0]), "+f"(c[1]), "+f"(c[2]), "+f"(c[3])
        : "r"(a[0]), "r"(a[1]), "r"(a[2]), "r"(a[3]), "r"(b[0]), "r"(b[1]));
}
// 64B-row swizzle: logical chunk c (0..3) of row r -> phys chunk c ^ ((r>>1)&3)
__device__ __forceinline__ uint32_t sw64(int r, int c) {
    return (uint32_t)r * 64u + (uint32_t)((c ^ ((r >> 1) & 3)) << 4);
}

// ---------------- conversion / transpose kernels ----------------
__global__ void split2_kernel(const float* __restrict__ inA, fp16* __restrict__ ohA, fp16* __restrict__ olA,
                              const float* __restrict__ inB, fp16* __restrict__ ohB, fp16* __restrict__ olB,
                              size_t n4) {
    size_t i = (size_t)blockIdx.x * blockDim.x + threadIdx.x;
    if (i >= n4) return;
    const float* in = blockIdx.y ? inB : inA;
    fp16* oh = blockIdx.y ? ohB : ohA;
    fp16* ol = blockIdx.y ? olB : olA;
    float4 v = ((const float4*)in)[i];
    fp16 h0 = __float2half_rn(v.x), h1 = __float2half_rn(v.y);
    fp16 h2 = __float2half_rn(v.z), h3 = __float2half_rn(v.w);
    ((__half2*)oh)[2 * i]     = __half2(h0, h1);
    ((__half2*)oh)[2 * i + 1] = __half2(h2, h3);
    ((__half2*)ol)[2 * i] = __half2(
        __float2half_rn(v.x - __half2float(h0)), __float2half_rn(v.y - __half2float(h1)));
    ((__half2*)ol)[2 * i + 1] = __half2(
        __float2half_rn(v.z - __half2float(h2)), __float2half_rn(v.w - __half2float(h3)));
}

// out[c][r] = in[r][c]; SPLIT=1 -> hi/lo, SPLIT=0 -> single
template <int SPLIT>
__global__ void transpose_fp16(const float* __restrict__ in, fp16* __restrict__ oh,
                               fp16* __restrict__ ol, int rows, int cols,
                               size_t ibs, size_t obs) {
    __shared__ float t[32][33];
    const float* I = in + (size_t)blockIdx.z * ibs;
    fp16* OH = oh + (size_t)blockIdx.z * obs;
    fp16* OL = SPLIT ? (ol + (size_t)blockIdx.z * obs) : nullptr;
    int c0 = blockIdx.x * 32, r0 = blockIdx.y * 32;
    int tx = threadIdx.x, ty = threadIdx.y;
    #pragma unroll
    for (int k = 0; k < 4; k++)
        t[ty + 8 * k][tx] = I[(size_t)(r0 + ty + 8 * k) * cols + c0 + tx];
    __syncthreads();
    #pragma unroll
    for (int k = 0; k < 4; k++) {
        float v = t[tx][ty + 8 * k];
        size_t o = (size_t)(c0 + ty + 8 * k) * rows + r0 + tx;
        fp16 h = __float2half_rn(v);
        OH[o] = h;
        if (SPLIT) OL[o] = __float2half_rn(v - __half2float(h));
    }
}

// ---------------- nonstandard masked softmax: S fp32 -> P fp16 ----------------
__global__ __launch_bounds__(256) void softmax_kernel(const float* __restrict__ Sb,
                                                      fp16* __restrict__ Pp) {
    const float* S = Sb + (size_t)blockIdx.x * Mm;
    fp16* P = Pp + (size_t)blockIdx.x * Mm;
    const int tid = threadIdx.x;

    float4 u0 = *(const float4*)&S[tid * 8];
    float4 u1 = *(const float4*)&S[tid * 8 + 4];
    float v[8] = {u0.x, u0.y, u0.z, u0.w, u1.x, u1.y, u1.z, u1.w};

    float mx = v[0];
    #pragma unroll
    for (int i = 1; i < 8; i++) mx = fmaxf(mx, v[i]);
    #pragma unroll
    for (int o = 16; o > 0; o >>= 1) mx = fmaxf(mx, __shfl_xor_sync(0xffffffffu, mx, o));

    __shared__ float red[8];
    const int wid = tid >> 5, lid = tid & 31;
    if (lid == 0) red[wid] = mx;
    __syncthreads();
    float rmax = red[0];
    #pragma unroll
    for (int w = 1; w < 8; w++) rmax = fmaxf(rmax, red[w]);
    __syncthreads();

    float e[8];
    float s = 0.f;
    #pragma unroll
    for (int i = 0; i < 8; i++) { e[i] = __expf(v[i] - rmax); s += e[i]; }
    #pragma unroll
    for (int o = 16; o > 0; o >>= 1) s += __shfl_xor_sync(0xffffffffu, s, o);
    if (lid == 0) red[wid] = s;
    __syncthreads();
    float tot = 0.f;
    #pragma unroll
    for (int w = 0; w < 8; w++) tot += red[w];
    const float inv = 1.f / tot;

    fp16 p[8];
    #pragma unroll
    for (int i = 0; i < 8; i++)
        p[i] = __float2half_rn((v[i] != 0.f) ? e[i] * inv : 0.f);
    *(uint4*)&P[tid * 8] = *(uint4*)p;
}

// ---------------- split-fp16 GEMM via mma.sync ----------------
// CTA tile: 128(M) x 64(N), K-step 32, 3-stage cp.async pipeline, 64B-row swizzle.
// A: [rows][K] hi (+lo if AS). B: [cols][K] hi (+lo if BS). C = A x B^T.
// Terms: Ah*Bh (+Ah*Bl if BS) (+Al*Bh if AS).
// EPI: 0 = *mask->f32 ; 1 = +bias->f32 ; 2 = relu(+bias)->fp16 ; 3 = dec*(1+tanh)->fp16
template <int EPI, int AS, int BS>
__global__ __launch_bounds__(256) void gemm_mma(
    const fp16* __restrict__ Ah, const fp16* __restrict__ Al,
    const fp16* __restrict__ Bh, const fp16* __restrict__ Bl,
    int Kd, size_t a_bs, size_t b_bs,
    const float* __restrict__ e0, size_t e0_bs, int e0_ld,
    float* __restrict__ outf, fp16* __restrict__ outh,
    size_t o_bs, int o_ld)
{
    constexpr int ACOMP = 8192;                    // 128 rows x 64 B
    constexpr int BCOMP = 4096;                    // 64 rows x 64 B
    constexpr int ABYTES = (1 + AS) * ACOMP;
    constexpr int STAGE = ABYTES + (1 + BS) * BCOMP;

    extern __shared__ char smem[];
    const uint32_t sb = smem_u32(smem);
    const int tid = threadIdx.x;
    const int wid = tid >> 5, lane = tid & 31;
    const int tC = blockIdx.x, tR = blockIdx.y, bz = blockIdx.z;
    const int NK = Kd >> 5;

    const fp16* A0h = Ah + (size_t)bz * a_bs + (size_t)(tR * 128) * Kd;
    const fp16* A0l = AS ? (Al + (size_t)bz * a_bs + (size_t)(tR * 128) * Kd) : nullptr;
    const fp16* B0h = Bh + (size_t)bz * b_bs + (size_t)(tC * 64) * Kd;
    const fp16* B0l = BS ? (Bl + (size_t)bz * b_bs + (size_t)(tC * 64) * Kd) : nullptr;

    auto load_stage = [&](int ks, int st) {
        const uint32_t base = sb + st * STAGE;
        const int k0 = ks * 32;
        #pragma unroll
        for (int j = 0; j < 2; j++) {
            const int id = tid + j * 256;
            const int r = id >> 2, c = id & 3;
            const size_t go = (size_t)r * Kd + k0 + c * 8;
            const uint32_t sw = sw64(r, c);
            cp_async16(base + sw, A0h + go);
            if (AS) cp_async16(base + ACOMP + sw, A0l + go);
        }
        {
            const int r = tid >> 2, c = tid & 3;
            const size_t go = (size_t)r * Kd + k0 + c * 8;
            const uint32_t sw = sw64(r, c);
            cp_async16(base + ABYTES + sw, B0h + go);
            if (BS) cp_async16(base + ABYTES + BCOMP + sw, B0l + go);
        }
        cp_commit();
    };

    const int m0 = (wid & 3) * 32;      // warp row offset (4 warps over 128 rows)
    const int n0 = (wid >> 2) * 32;     // warp col offset (2 warps over 64 cols)

    float acc[2][4][4];
    #pragma unroll
    for (int mt = 0; mt < 2; mt++)
        #pragma unroll
        for (int nt = 0; nt < 4; nt++)
            #pragma unroll
            for (int q = 0; q < 4; q++) acc[mt][nt][q] = 0.f;

    load_stage(0, 0);
    load_stage(1, 1);

    for (int ks = 0; ks < NK; ks++) {
        if (ks + 1 < NK) cp_wait<1>(); else cp_wait<0>();
        __syncthreads();
        if (ks + 2 < NK) load_stage(ks + 2, (ks + 2) % 3);

        const uint32_t base = sb + (ks % 3) * STAGE;
        #pragma unroll
        for (int kk = 0; kk < 2; kk++) {
            const int c0 = kk * 2;
            uint32_t ah[2][4], al[2][4], bh[4][2], bl[4][2];
            #pragma unroll
            for (int mt = 0; mt < 2; mt++) {
                const int row = m0 + mt * 16 + (lane & 15);
                const int ch = c0 + (lane >> 4);
                const uint32_t ad = base + sw64(row, ch);
                ldsm_x4(ah[mt], ad);
                if (AS) ldsm_x4(al[mt], ad + ACOMP);
            }
            #pragma unroll
            for (int g = 0; g < 2; g++) {
                const int row = n0 + g * 16 + ((lane >> 4) << 3) + (lane & 7);
                const int ch = c0 + ((lane >> 3) & 1);
                const uint32_t bd = base + ABYTES + sw64(row, ch);
                uint32_t t[4];
                ldsm_x4(t, bd);
                bh[g * 2][0] = t[0]; bh[g * 2][1] = t[1];
                bh[g * 2 + 1][0] = t[2]; bh[g * 2 + 1][1] = t[3];
                if (BS) {
                    ldsm_x4(t, bd + BCOMP);
                    bl[g * 2][0] = t[0]; bl[g * 2][1] = t[1];
                    bl[g * 2 + 1][0] = t[2]; bl[g * 2 + 1][1] = t[3];
                }
            }
            #pragma unroll
            for (int mt = 0; mt < 2; mt++)
                #pragma unroll
                for (int nt = 0; nt < 4; nt++) {
                    mma16816(acc[mt][nt], ah[mt], bh[nt]);
                    if (BS) mma16816(acc[mt][nt], ah[mt], bl[nt]);
                    if (AS) mma16816(acc[mt][nt], al[mt], bh[nt]);
                }
        }
    }

    // ---- epilogue
    const int grb = tR * 128 + m0;
    const int gcb = tC * 64 + n0;
    #pragma unroll
    for (int mt = 0; mt < 2; mt++) {
        #pragma unroll
        for (int rr = 0; rr < 2; rr++) {
            const int row = grb + mt * 16 + rr * 8 + (lane >> 2);
            #pragma unroll
            for (int nt = 0; nt < 4; nt++) {
                const int col = gcb + nt * 8 + 2 * (lane & 3);
                float v0 = acc[mt][nt][rr * 2 + 0];
                float v1 = acc[mt][nt][rr * 2 + 1];
                if (EPI == 0) {
                    const float2 mk = *(const float2*)&e0[(size_t)bz * e0_bs + (size_t)row * e0_ld + col];
                    *(float2*)&outf[(size_t)bz * o_bs + (size_t)row * o_ld + col] =
                        make_float2(v0 * mk.x, v1 * mk.y);
                } else if (EPI == 1) {
                    const float2 b = *(const float2*)&e0[col];
                    *(float2*)&outf[(size_t)bz * o_bs + (size_t)row * o_ld + col] =
                        make_float2(v0 + b.x, v1 + b.y);
                } else if (EPI == 2) {
                    const float2 b = *(const float2*)&e0[col];
                    float g0 = fmaxf(v0 + b.x, 0.f), g1 = fmaxf(v1 + b.y, 0.f);
                    *(__half2*)&outh[(size_t)bz * o_bs + (size_t)row * o_ld + col] =
                        __half2(__float2half_rn(g0), __float2half_rn(g1));
                } else {
                    const float2 dd = *(const float2*)&e0[(size_t)bz * e0_bs + (size_t)row * e0_ld + col];
                    float g0 = dd.x * (1.f + tanhf(v0));
                    float g1 = dd.y * (1.f + tanhf(v1));
                    *(__half2*)&outh[(size_t)bz * o_bs + (size_t)row * o_ld + col] =
                        __half2(__float2half_rn(g0), __float2half_rn(g1));
                }
            }
        }
    }
}

// ---------------- host launch ----------------
extern "C" void kernel_launch(void* const* d_in, const int* in_sizes, int n_in,
                              void* d_out, int out_size)
{
    const float* dec  = (const float*)d_in[0];
    const float* enc  = (const float*)d_in[1];
    const float* mask = (const float*)d_in[2];
    const float* Wv   = (const float*)d_in[3];
    const float* bv   = (const float*)d_in[4];
    const float* W1   = (const float*)d_in[5];
    const float* b1   = (const float*)d_in[6];
    const float* W2   = (const float*)d_in[7];
    const float* b2   = (const float*)d_in[8];
    float* out = (float*)d_out;

    float *S, *Vf;
    fp16 *P, *dch, *dcl, *ech, *ecl, *VT, *G, *H;
    fp16 *WvT, *W1T, *W2T;
    cudaGetSymbolAddress((void**)&S, S_buf);
    cudaGetSymbolAddress((void**)&Vf, Vf_buf);
    cudaGetSymbolAddress((void**)&P, P_buf);
    cudaGetSymbolAddress((void**)&dch, dech_buf); cudaGetSymbolAddress((void**)&dcl, decl_buf);
    cudaGetSymbolAddress((void**)&ech, ench_buf); cudaGetSymbolAddress((void**)&ecl, encl_buf);
    cudaGetSymbolAddress((void**)&VT, VT_buf);
    cudaGetSymbolAddress((void**)&G, G_buf);     cudaGetSymbolAddress((void**)&H, H_buf);
    cudaGetSymbolAddress((void**)&WvT, WvT_buf);
    cudaGetSymbolAddress((void**)&W1T, W1T_buf);
    cudaGetSymbolAddress((void**)&W2T, W2T_buf);

    // 3-stage smem footprints
    constexpr int SM_3T = 3 * (2 * 8192 + 2 * 4096);   // 73728 (AS=1,BS=1) scores
    constexpr int SM_A  = 3 * (2 * 8192 + 1 * 4096);   // 61440 (AS=1,BS=0) Vf
    constexpr int SM_00 = 3 * (1 * 8192 + 1 * 4096);   // 36864 (AS=0,BS=0) PV/fc
    cudaFuncSetAttribute(gemm_mma<0,1,1>, cudaFuncAttributeMaxDynamicSharedMemorySize, SM_3T);
    cudaFuncSetAttribute(gemm_mma<1,1,0>, cudaFuncAttributeMaxDynamicSharedMemorySize, SM_A);
    cudaFuncSetAttribute(gemm_mma<3,0,0>, cudaFuncAttributeMaxDynamicSharedMemorySize, SM_00);
    cudaFuncSetAttribute(gemm_mma<2,0,0>, cudaFuncAttributeMaxDynamicSharedMemorySize, SM_00);
    cudaFuncSetAttribute(gemm_mma<1,0,0>, cudaFuncAttributeMaxDynamicSharedMemorySize, SM_00);

    const size_t nEmb = (size_t)Bb * Nn * Cc;       // 8M elems

    // 1) split dec & enc to fp16 hi/lo (one launch)
    split2_kernel<<<dim3((unsigned)(nEmb / 4 / 256), 2), 256>>>(
        dec, dch, dcl, enc, ech, ecl, nEmb / 4);

    // 2) weight transposes: all single fp16
    dim3 tb(32, 8);
    transpose_fp16<0><<<dim3(Cc / 32, Cc / 32, 1), tb>>>(Wv, WvT, nullptr, Cc, Cc, 0, 0);
    transpose_fp16<0><<<dim3(Cc / 32, Cc / 32, 1), tb>>>(W1, W1T, nullptr, Cc, Cc, 0, 0);
    transpose_fp16<0><<<dim3(Cc / 32, Cc / 32, 1), tb>>>(W2, W2T, nullptr, Cc, Cc, 0, 0);

    // 3) Vf = enc @ Wv + bv (fp32): A=enc split, B=WvT single
    gemm_mma<1,1,0><<<dim3(Cc / 64, (Bb * Mm) / 128, 1), 256, SM_A>>>(
        ech, ecl, WvT, nullptr, Cc, 0, 0,
        bv, 0, 0, Vf, nullptr, 0, Cc);

    // 4) VT = transpose(Vf) -> fp16 single  [B][C][M]
    transpose_fp16<0><<<dim3(Cc / 32, Mm / 32, Bb), tb>>>(
        Vf, VT, nullptr, Mm, Cc, (size_t)Mm * Cc, (size_t)Cc * Mm);

    // 5) S = (dec @ enc^T) * mask (fp32): 3-term
    gemm_mma<0,1,1><<<dim3(Mm / 64, Nn / 128, Bb), 256, SM_3T>>>(
        dch, dcl, ech, ecl, Cc, (size_t)Nn * Cc, (size_t)Mm * Cc,
        mask, (size_t)Nn * Mm, Mm, S, nullptr, (size_t)Nn * Mm, Mm);

    // 6) softmax -> P fp16 single
    softmax_kernel<<<Bb * Nn, 256>>>(S, P);

    // 7) G = dec * (1 + tanh(P @ V)) -> fp16: A=P single, B=VT single
    gemm_mma<3,0,0><<<dim3(Cc / 64, Nn / 128, Bb), 256, SM_00>>>(
        P, nullptr, VT, nullptr, Mm, (size_t)Nn * Mm, (size_t)Cc * Mm,
        dec, (size_t)Nn * Cc, Cc, nullptr, G, (size_t)Nn * Cc, Cc);

    // 8) H = relu(G @ W1 + b1) -> fp16: single x single
    gemm_mma<2,0,0><<<dim3(Cc / 64, (Bb * Nn) / 128, 1), 256, SM_00>>>(
        G, nullptr, W1T, nullptr, Cc, 0, 0,
        b1, 0, 0, nullptr, H, 0, Cc);

    // 9) out = H @ W2 + b2 (fp32): single x single
    gemm_mma<1,0,0><<<dim3(Cc / 64, (Bb * Nn) / 128, 1), 256, SM_00>>>(
        H, nullptr, W2T, nullptr, Cc, 0, 0,
        b2, 0, 0, out, nullptr, 0, Cc);
}

// round 7
// speedup vs baseline: 4.8161x; 1.0263x over previous
#include <cuda_runtime.h>
#include <cuda_fp16.h>
#include <cstdint>
#include <math.h>

typedef __half fp16;

static constexpr int Bb = 8, Nn = 2048, Mm = 2048, Cc = 512;

// ---------------- scratch (__device__ globals; no allocations) ----------------
__device__ float S_buf [(size_t)Bb * Nn * Mm];          // scores fp32 (128 MiB)
__device__ fp16  P_buf [(size_t)Bb * Nn * Mm];          // softmax probs (single fp16)
__device__ fp16  dech_buf[(size_t)Bb * Nn * Cc], decl_buf[(size_t)Bb * Nn * Cc];
__device__ fp16  ench_buf[(size_t)Bb * Mm * Cc], encl_buf[(size_t)Bb * Mm * Cc];
__device__ float Vf_buf [(size_t)Bb * Mm * Cc];         // enc@Wv+bv fp32
__device__ fp16  VT_buf [(size_t)Bb * Cc * Mm];         // V^T single fp16
__device__ fp16  G_buf[(size_t)Bb * Nn * Cc];           // gated, single fp16
__device__ fp16  H_buf[(size_t)Bb * Nn * Cc];           // relu(fc1), single fp16
__device__ fp16  WvT_buf[Cc * Cc];
__device__ fp16  W1T_buf[Cc * Cc];
__device__ fp16  W2T_buf[Cc * Cc];

// ---------------- arch-neutral PTX helpers ----------------
__device__ __forceinline__ uint32_t smem_u32(const void* p) {
    uint32_t a;
    asm("{ .reg .u64 t; cvta.to.shared.u64 t, %1; cvt.u32.u64 %0, t; }" : "=r"(a) : "l"(p));
    return a;
}
__device__ __forceinline__ void cp_async16(uint32_t dst, const void* src) {
    asm volatile("cp.async.cg.shared.global [%0], [%1], 16;" :: "r"(dst), "l"(src) : "memory");
}
__device__ __forceinline__ void cp_commit() { asm volatile("cp.async.commit_group;" ::: "memory"); }
template <int N> __device__ __forceinline__ void cp_wait() {
    asm volatile("cp.async.wait_group %0;" :: "n"(N) : "memory");
}
__device__ __forceinline__ void ldsm_x4(uint32_t* r, uint32_t addr) {
    asm volatile("ldmatrix.sync.aligned.m8n8.x4.shared.b16 {%0,%1,%2,%3}, [%4];"
        : "=r"(r[0]), "=r"(r[1]), "=r"(r[2]), "=r"(r[3]) : "r"(addr));
}
__device__ __forceinline__ void mma16816(float* c, const uint32_t* a, const uint32_t* b) {
    asm volatile("mma.sync.aligned.m16n8k16.row.col.f32.f16.f16.f32 "
        "{%0,%1,%2,%3}, {%4,%5,%6,%7}, {%8,%9}, {%0,%1,%2,%3};"
        : "+f"(c[0]), "+f"(c[1]), "+f"(c[2]), "+f"(c[3])
        : "r"(a[0]), "r"(a[1]), "r"(a[2]), "r"(a[3]), "r"(b[0]), "r"(b[1]));
}
// 64B-row swizzle: logical chunk c (0..3) of row r -> phys chunk c ^ ((r>>1)&3)
__device__ __forceinline__ uint32_t sw64(int r, int c) {
    return (uint32_t)r * 64u + (uint32_t)((c ^ ((r >> 1) & 3)) << 4);
}

// ---------------- conversion / transpose kernels ----------------
__global__ void split2_kernel(const float* __restrict__ inA, fp16* __restrict__ ohA, fp16* __restrict__ olA,
                              const float* __restrict__ inB, fp16* __restrict__ ohB, fp16* __restrict__ olB,
                              size_t n4) {
    size_t i = (size_t)blockIdx.x * blockDim.x + threadIdx.x;
    if (i >= n4) return;
    const float* in = blockIdx.y ? inB : inA;
    fp16* oh = blockIdx.y ? ohB : ohA;
    fp16* ol = blockIdx.y ? olB : olA;
    float4 v = ((const float4*)in)[i];
    fp16 h0 = __float2half_rn(v.x), h1 = __float2half_rn(v.y);
    fp16 h2 = __float2half_rn(v.z), h3 = __float2half_rn(v.w);
    ((__half2*)oh)[2 * i]     = __half2(h0, h1);
    ((__half2*)oh)[2 * i + 1] = __half2(h2, h3);
    ((__half2*)ol)[2 * i] = __half2(
        __float2half_rn(v.x - __half2float(h0)), __float2half_rn(v.y - __half2float(h1)));
    ((__half2*)ol)[2 * i + 1] = __half2(
        __float2half_rn(v.z - __half2float(h2)), __float2half_rn(v.w - __half2float(h3)));
}

// out[c][r] = in[r][c]; SPLIT=1 -> hi/lo, SPLIT=0 -> single
template <int SPLIT>
__global__ void transpose_fp16(const float* __restrict__ in, fp16* __restrict__ oh,
                               fp16* __restrict__ ol, int rows, int cols,
                               size_t ibs, size_t obs) {
    __shared__ float t[32][33];
    const float* I = in + (size_t)blockIdx.z * ibs;
    fp16* OH = oh + (size_t)blockIdx.z * obs;
    fp16* OL = SPLIT ? (ol + (size_t)blockIdx.z * obs) : nullptr;
    int c0 = blockIdx.x * 32, r0 = blockIdx.y * 32;
    int tx = threadIdx.x, ty = threadIdx.y;
    #pragma unroll
    for (int k = 0; k < 4; k++)
        t[ty + 8 * k][tx] = I[(size_t)(r0 + ty + 8 * k) * cols + c0 + tx];
    __syncthreads();
    #pragma unroll
    for (int k = 0; k < 4; k++) {
        float v = t[tx][ty + 8 * k];
        size_t o = (size_t)(c0 + ty + 8 * k) * rows + r0 + tx;
        fp16 h = __float2half_rn(v);
        OH[o] = h;
        if (SPLIT) OL[o] = __float2half_rn(v - __half2float(h));
    }
}

// ---------------- nonstandard masked softmax: S fp32 -> P fp16 ----------------
__global__ __launch_bounds__(256) void softmax_kernel(const float* __restrict__ Sb,
                                                      fp16* __restrict__ Pp) {
    const float* S = Sb + (size_t)blockIdx.x * Mm;
    fp16* P = Pp + (size_t)blockIdx.x * Mm;
    const int tid = threadIdx.x;

    float4 u0 = *(const float4*)&S[tid * 8];
    float4 u1 = *(const float4*)&S[tid * 8 + 4];
    float v[8] = {u0.x, u0.y, u0.z, u0.w, u1.x, u1.y, u1.z, u1.w};

    float mx = v[0];
    #pragma unroll
    for (int i = 1; i < 8; i++) mx = fmaxf(mx, v[i]);
    #pragma unroll
    for (int o = 16; o > 0; o >>= 1) mx = fmaxf(mx, __shfl_xor_sync(0xffffffffu, mx, o));

    __shared__ float red[8];
    const int wid = tid >> 5, lid = tid & 31;
    if (lid == 0) red[wid] = mx;
    __syncthreads();
    float rmax = red[0];
    #pragma unroll
    for (int w = 1; w < 8; w++) rmax = fmaxf(rmax, red[w]);
    __syncthreads();

    float e[8];
    float s = 0.f;
    #pragma unroll
    for (int i = 0; i < 8; i++) { e[i] = __expf(v[i] - rmax); s += e[i]; }
    #pragma unroll
    for (int o = 16; o > 0; o >>= 1) s += __shfl_xor_sync(0xffffffffu, s, o);
    if (lid == 0) red[wid] = s;
    __syncthreads();
    float tot = 0.f;
    #pragma unroll
    for (int w = 0; w < 8; w++) tot += red[w];
    const float inv = 1.f / tot;

    fp16 p[8];
    #pragma unroll
    for (int i = 0; i < 8; i++)
        p[i] = __float2half_rn((v[i] != 0.f) ? e[i] * inv : 0.f);
    *(uint4*)&P[tid * 8] = *(uint4*)p;
}

// ---------------- split-fp16 GEMM via mma.sync ----------------
// CTA tile: 128(M) x 64(N), K-step 32, 3-stage cp.async pipeline, 64B-row swizzle.
// A: [rows][K] hi (+lo if AS). B: [cols][K] hi (+lo if BS). C = A x B^T.
// Terms: Ah*Bh (+Ah*Bl if BS) (+Al*Bh if AS).
// EPI: 0 = *mask->f32 ; 1 = +bias->f32 ; 2 = relu(+bias)->fp16 ; 3 = dec*(1+tanh)->fp16
template <int EPI, int AS, int BS>
__global__ __launch_bounds__(256) void gemm_mma(
    const fp16* __restrict__ Ah, const fp16* __restrict__ Al,
    const fp16* __restrict__ Bh, const fp16* __restrict__ Bl,
    int Kd, size_t a_bs, size_t b_bs,
    const float* __restrict__ e0, size_t e0_bs, int e0_ld,
    float* __restrict__ outf, fp16* __restrict__ outh,
    size_t o_bs, int o_ld)
{
    constexpr int ACOMP = 8192;                    // 128 rows x 64 B
    constexpr int BCOMP = 4096;                    // 64 rows x 64 B
    constexpr int ABYTES = (1 + AS) * ACOMP;
    constexpr int STAGE = ABYTES + (1 + BS) * BCOMP;

    extern __shared__ char smem[];
    const uint32_t sb = smem_u32(smem);
    const int tid = threadIdx.x;
    const int wid = tid >> 5, lane = tid & 31;
    const int tC = blockIdx.x, tR = blockIdx.y, bz = blockIdx.z;
    const int NK = Kd >> 5;

    const fp16* A0h = Ah + (size_t)bz * a_bs + (size_t)(tR * 128) * Kd;
    const fp16* A0l = AS ? (Al + (size_t)bz * a_bs + (size_t)(tR * 128) * Kd) : nullptr;
    const fp16* B0h = Bh + (size_t)bz * b_bs + (size_t)(tC * 64) * Kd;
    const fp16* B0l = BS ? (Bl + (size_t)bz * b_bs + (size_t)(tC * 64) * Kd) : nullptr;

    auto load_stage = [&](int ks, int st) {
        const uint32_t base = sb + st * STAGE;
        const int k0 = ks * 32;
        #pragma unroll
        for (int j = 0; j < 2; j++) {
            const int id = tid + j * 256;
            const int r = id >> 2, c = id & 3;
            const size_t go = (size_t)r * Kd + k0 + c * 8;
            const uint32_t sw = sw64(r, c);
            cp_async16(base + sw, A0h + go);
            if (AS) cp_async16(base + ACOMP + sw, A0l + go);
        }
        {
            const int r = tid >> 2, c = tid & 3;
            const size_t go = (size_t)r * Kd + k0 + c * 8;
            const uint32_t sw = sw64(r, c);
            cp_async16(base + ABYTES + sw, B0h + go);
            if (BS) cp_async16(base + ABYTES + BCOMP + sw, B0l + go);
        }
        cp_commit();
    };

    const int m0 = (wid & 3) * 32;      // warp row offset (4 warps over 128 rows)
    const int n0 = (wid >> 2) * 32;     // warp col offset (2 warps over 64 cols)

    float acc[2][4][4];
    #pragma unroll
    for (int mt = 0; mt < 2; mt++)
        #pragma unroll
        for (int nt = 0; nt < 4; nt++)
            #pragma unroll
            for (int q = 0; q < 4; q++) acc[mt][nt][q] = 0.f;

    load_stage(0, 0);
    load_stage(1, 1);

    for (int ks = 0; ks < NK; ks++) {
        if (ks + 1 < NK) cp_wait<1>(); else cp_wait<0>();
        __syncthreads();
        if (ks + 2 < NK) load_stage(ks + 2, (ks + 2) % 3);

        const uint32_t base = sb + (ks % 3) * STAGE;
        #pragma unroll
        for (int kk = 0; kk < 2; kk++) {
            const int c0 = kk * 2;
            uint32_t ah[2][4], al[2][4], bh[4][2], bl[4][2];
            #pragma unroll
            for (int mt = 0; mt < 2; mt++) {
                const int row = m0 + mt * 16 + (lane & 15);
                const int ch = c0 + (lane >> 4);
                const uint32_t ad = base + sw64(row, ch);
                ldsm_x4(ah[mt], ad);
                if (AS) ldsm_x4(al[mt], ad + ACOMP);
            }
            #pragma unroll
            for (int g = 0; g < 2; g++) {
                const int row = n0 + g * 16 + ((lane >> 4) << 3) + (lane & 7);
                const int ch = c0 + ((lane >> 3) & 1);
                const uint32_t bd = base + ABYTES + sw64(row, ch);
                uint32_t t[4];
                ldsm_x4(t, bd);
                bh[g * 2][0] = t[0]; bh[g * 2][1] = t[1];
                bh[g * 2 + 1][0] = t[2]; bh[g * 2 + 1][1] = t[3];
                if (BS) {
                    ldsm_x4(t, bd + BCOMP);
                    bl[g * 2][0] = t[0]; bl[g * 2][1] = t[1];
                    bl[g * 2 + 1][0] = t[2]; bl[g * 2 + 1][1] = t[3];
                }
            }
            #pragma unroll
            for (int mt = 0; mt < 2; mt++)
                #pragma unroll
                for (int nt = 0; nt < 4; nt++) {
                    mma16816(acc[mt][nt], ah[mt], bh[nt]);
                    if (BS) mma16816(acc[mt][nt], ah[mt], bl[nt]);
                    if (AS) mma16816(acc[mt][nt], al[mt], bh[nt]);
                }
        }
    }

    // ---- epilogue
    const int grb = tR * 128 + m0;
    const int gcb = tC * 64 + n0;
    #pragma unroll
    for (int mt = 0; mt < 2; mt++) {
        #pragma unroll
        for (int rr = 0; rr < 2; rr++) {
            const int row = grb + mt * 16 + rr * 8 + (lane >> 2);
            #pragma unroll
            for (int nt = 0; nt < 4; nt++) {
                const int col = gcb + nt * 8 + 2 * (lane & 3);
                float v0 = acc[mt][nt][rr * 2 + 0];
                float v1 = acc[mt][nt][rr * 2 + 1];
                if (EPI == 0) {
                    const float2 mk = *(const float2*)&e0[(size_t)bz * e0_bs + (size_t)row * e0_ld + col];
                    *(float2*)&outf[(size_t)bz * o_bs + (size_t)row * o_ld + col] =
                        make_float2(v0 * mk.x, v1 * mk.y);
                } else if (EPI == 1) {
                    const float2 b = *(const float2*)&e0[col];
                    *(float2*)&outf[(size_t)bz * o_bs + (size_t)row * o_ld + col] =
                        make_float2(v0 + b.x, v1 + b.y);
                } else if (EPI == 2) {
                    const float2 b = *(const float2*)&e0[col];
                    float g0 = fmaxf(v0 + b.x, 0.f), g1 = fmaxf(v1 + b.y, 0.f);
                    *(__half2*)&outh[(size_t)bz * o_bs + (size_t)row * o_ld + col] =
                        __half2(__float2half_rn(g0), __float2half_rn(g1));
                } else {
                    const float2 dd = *(const float2*)&e0[(size_t)bz * e0_bs + (size_t)row * e0_ld + col];
                    float g0 = dd.x * (1.f + tanhf(v0));
                    float g1 = dd.y * (1.f + tanhf(v1));
                    *(__half2*)&outh[(size_t)bz * o_bs + (size_t)row * o_ld + col] =
                        __half2(__float2half_rn(g0), __float2half_rn(g1));
                }
            }
        }
    }
}

// ---------------- host launch ----------------
extern "C" void kernel_launch(void* const* d_in, const int* in_sizes, int n_in,
                              void* d_out, int out_size)
{
    const float* dec  = (const float*)d_in[0];
    const float* enc  = (const float*)d_in[1];
    const float* mask = (const float*)d_in[2];
    const float* Wv   = (const float*)d_in[3];
    const float* bv   = (const float*)d_in[4];
    const float* W1   = (const float*)d_in[5];
    const float* b1   = (const float*)d_in[6];
    const float* W2   = (const float*)d_in[7];
    const float* b2   = (const float*)d_in[8];
    float* out = (float*)d_out;

    float *S, *Vf;
    fp16 *P, *dch, *dcl, *ech, *ecl, *VT, *G, *H;
    fp16 *WvT, *W1T, *W2T;
    cudaGetSymbolAddress((void**)&S, S_buf);
    cudaGetSymbolAddress((void**)&Vf, Vf_buf);
    cudaGetSymbolAddress((void**)&P, P_buf);
    cudaGetSymbolAddress((void**)&dch, dech_buf); cudaGetSymbolAddress((void**)&dcl, decl_buf);
    cudaGetSymbolAddress((void**)&ech, ench_buf); cudaGetSymbolAddress((void**)&ecl, encl_buf);
    cudaGetSymbolAddress((void**)&VT, VT_buf);
    cudaGetSymbolAddress((void**)&G, G_buf);     cudaGetSymbolAddress((void**)&H, H_buf);
    cudaGetSymbolAddress((void**)&WvT, WvT_buf);
    cudaGetSymbolAddress((void**)&W1T, W1T_buf);
    cudaGetSymbolAddress((void**)&W2T, W2T_buf);

    // Lazy-created side stream + fork/join events (host-side resources only;
    // created on the first, uncaptured correctness call, reused under capture).
    static cudaStream_t sB = nullptr;
    static cudaEvent_t evFork = nullptr, evJoin = nullptr;
    if (!sB) {
        cudaStreamCreateWithFlags(&sB, cudaStreamNonBlocking);
        cudaEventCreateWithFlags(&evFork, cudaEventDisableTiming);
        cudaEventCreateWithFlags(&evJoin, cudaEventDisableTiming);
    }

    // 3-stage smem footprints
    constexpr int SM_3T = 3 * (2 * 8192 + 2 * 4096);   // 73728 (AS=1,BS=1) scores
    constexpr int SM_A  = 3 * (2 * 8192 + 1 * 4096);   // 61440 (AS=1,BS=0) Vf
    constexpr int SM_00 = 3 * (1 * 8192 + 1 * 4096);   // 36864 (AS=0,BS=0) PV/fc
    cudaFuncSetAttribute(gemm_mma<0,1,1>, cudaFuncAttributeMaxDynamicSharedMemorySize, SM_3T);
    cudaFuncSetAttribute(gemm_mma<1,1,0>, cudaFuncAttributeMaxDynamicSharedMemorySize, SM_A);
    cudaFuncSetAttribute(gemm_mma<3,0,0>, cudaFuncAttributeMaxDynamicSharedMemorySize, SM_00);
    cudaFuncSetAttribute(gemm_mma<2,0,0>, cudaFuncAttributeMaxDynamicSharedMemorySize, SM_00);
    cudaFuncSetAttribute(gemm_mma<1,0,0>, cudaFuncAttributeMaxDynamicSharedMemorySize, SM_00);

    const size_t nEmb = (size_t)Bb * Nn * Cc;       // 8M elems
    dim3 tb(32, 8);

    // 1) split dec & enc to fp16 hi/lo (origin stream)
    split2_kernel<<<dim3((unsigned)(nEmb / 4 / 256), 2), 256>>>(
        dec, dch, dcl, enc, ech, ecl, nEmb / 4);

    // ---- fork: side stream runs the V-producer chain + weight transposes
    cudaEventRecord(evFork, 0);
    cudaStreamWaitEvent(sB, evFork, 0);

    transpose_fp16<0><<<dim3(Cc / 32, Cc / 32, 1), tb, 0, sB>>>(Wv, WvT, nullptr, Cc, Cc, 0, 0);
    transpose_fp16<0><<<dim3(Cc / 32, Cc / 32, 1), tb, 0, sB>>>(W1, W1T, nullptr, Cc, Cc, 0, 0);
    transpose_fp16<0><<<dim3(Cc / 32, Cc / 32, 1), tb, 0, sB>>>(W2, W2T, nullptr, Cc, Cc, 0, 0);

    // Vf = enc @ Wv + bv (fp32): A=enc split, B=WvT single
    gemm_mma<1,1,0><<<dim3(Cc / 64, (Bb * Mm) / 128, 1), 256, SM_A, sB>>>(
        ech, ecl, WvT, nullptr, Cc, 0, 0,
        bv, 0, 0, Vf, nullptr, 0, Cc);

    // VT = transpose(Vf) -> fp16 single  [B][C][M]
    transpose_fp16<0><<<dim3(Cc / 32, Mm / 32, Bb), tb, 0, sB>>>(
        Vf, VT, nullptr, Mm, Cc, (size_t)Mm * Cc, (size_t)Cc * Mm);

    cudaEventRecord(evJoin, sB);

    // ---- origin stream: scores + softmax (overlaps with side stream)
    gemm_mma<0,1,1><<<dim3(Mm / 64, Nn / 128, Bb), 256, SM_3T>>>(
        dch, dcl, ech, ecl, Cc, (size_t)Nn * Cc, (size_t)Mm * Cc,
        mask, (size_t)Nn * Mm, Mm, S, nullptr, (size_t)Nn * Mm, Mm);

    softmax_kernel<<<Bb * Nn, 256>>>(S, P);

    // ---- join: PV needs VT
    cudaStreamWaitEvent(0, evJoin, 0);

    // G = dec * (1 + tanh(P @ V)) -> fp16: single x single
    gemm_mma<3,0,0><<<dim3(Cc / 64, Nn / 128, Bb), 256, SM_00>>>(
        P, nullptr, VT, nullptr, Mm, (size_t)Nn * Mm, (size_t)Cc * Mm,
        dec, (size_t)Nn * Cc, Cc, nullptr, G, (size_t)Nn * Cc, Cc);

    // H = relu(G @ W1 + b1) -> fp16: single x single
    gemm_mma<2,0,0><<<dim3(Cc / 64, (Bb * Nn) / 128, 1), 256, SM_00>>>(
        G, nullptr, W1T, nullptr, Cc, 0, 0,
        b1, 0, 0, nullptr, H, 0, Cc);

    // out = H @ W2 + b2 (fp32): single x single
    gemm_mma<1,0,0><<<dim3(Cc / 64, (Bb * Nn) / 128, 1), 256, SM_00>>>(
        H, nullptr, W2T, nullptr, Cc, 0, 0,
        b2, 0, 0, out, nullptr, 0, Cc);
}